// round 6
// baseline (speedup 1.0000x reference)
#include <cuda_runtime.h>
#include <cuda_fp16.h>

#define N_NODES 200000
#define N_EDGES 6400000
#define D_IN    100
#define D_H1    65
#define H1P     68      // fp32 compute pad (17 float4)
#define H1H     72      // fp16 row pad: 9 x uint4 (8 halves each) = 144B
#define D_H2    64      // fp16 row: 8 x uint4 = 128B

#define SCAN_B  1024
#define SCAN_NB ((N_NODES + SCAN_B - 1) / SCAN_B)   // 196

// ---------------- scratch (device globals; no allocation allowed) -----------
__device__ uint4  g_h1h [(N_NODES * H1H) / 8];   // 28.8 MB  fp16 h1*dinv (L2-resident)
__device__ uint4  g_h2h [(N_NODES * D_H2) / 8];  // 25.6 MB  fp16 h2*dinv (L2-resident)
__device__ float  g_dinv[N_NODES];
__device__ int    g_deg [N_NODES];
__device__ int    g_rowptr[N_NODES + 1];
__device__ int    g_cursor[N_NODES];
__device__ int    g_esrc[N_EDGES];               // CSR: src ids grouped by dst
__device__ int    g_bsum[SCAN_NB];               // per-block scan totals

// ---------------- degree / dinv ---------------------------------------------
__global__ void k_deg_zero() {
    int i = blockIdx.x * blockDim.x + threadIdx.x;
    if (i < N_NODES) g_deg[i] = 0;
}

__global__ void k_deg_count(const int* __restrict__ ei) {
    int e = blockIdx.x * blockDim.x + threadIdx.x;
    if (e < N_EDGES) atomicAdd(&g_deg[ei[N_EDGES + e]], 1);   // dst = ei[1]
}

__global__ void k_dinv() {
    int i = blockIdx.x * blockDim.x + threadIdx.x;
    if (i < N_NODES) g_dinv[i] = rsqrtf((float)(g_deg[i] + 1));  // +1 self loop
}

// ---------------- scan pass 1: per-block exclusive scan ----------------------
__global__ __launch_bounds__(SCAN_B) void k_scan1() {
    __shared__ int wsum[32];
    int t = threadIdx.x, lane = t & 31, wid = t >> 5;
    int idx = blockIdx.x * SCAN_B + t;
    int v = (idx < N_NODES) ? g_deg[idx] : 0;
    int x = v;
#pragma unroll
    for (int off = 1; off < 32; off <<= 1) {
        int n = __shfl_up_sync(0xffffffffu, x, off);
        if (lane >= off) x += n;
    }
    if (lane == 31) wsum[wid] = x;
    __syncthreads();
    if (wid == 0) {
        int w = wsum[lane];
#pragma unroll
        for (int off = 1; off < 32; off <<= 1) {
            int n = __shfl_up_sync(0xffffffffu, w, off);
            if (lane >= off) w += n;
        }
        wsum[lane] = w;   // inclusive warp totals
    }
    __syncthreads();
    int warpoff = (wid > 0) ? wsum[wid - 1] : 0;
    int excl = x - v + warpoff;                    // block-local exclusive
    if (idx < N_NODES) g_rowptr[idx] = excl;
    if (t == SCAN_B - 1) g_bsum[blockIdx.x] = warpoff + x;   // block total
}

// ---------------- scan pass 2: scan the 196 block totals (1 tiny block) -----
__global__ __launch_bounds__(256) void k_scan2() {
    __shared__ int wsum[8];
    int t = threadIdx.x, lane = t & 31, wid = t >> 5;
    int v = (t < SCAN_NB) ? g_bsum[t] : 0;
    int x = v;
#pragma unroll
    for (int off = 1; off < 32; off <<= 1) {
        int n = __shfl_up_sync(0xffffffffu, x, off);
        if (lane >= off) x += n;
    }
    if (lane == 31) wsum[wid] = x;
    __syncthreads();
    if (wid == 0 && lane < 8) {
        int w = wsum[lane];
#pragma unroll
        for (int off = 1; off < 8; off <<= 1) {
            int n = __shfl_up_sync(0xffu, w, off);
            if (lane >= off) w += n;
        }
        wsum[lane] = w;
    }
    __syncthreads();
    int warpoff = (wid > 0) ? wsum[wid - 1] : 0;
    int excl = x - v + warpoff;
    if (t < SCAN_NB) g_bsum[t] = excl;
    if (t == SCAN_NB - 1) g_rowptr[N_NODES] = excl + v;   // grand total
}

// ---------------- scan pass 3: add block offsets, init cursor ----------------
__global__ __launch_bounds__(SCAN_B) void k_scan3() {
    int idx = blockIdx.x * SCAN_B + threadIdx.x;
    if (idx < N_NODES) {
        int r = g_rowptr[idx] + g_bsum[blockIdx.x];
        g_rowptr[idx] = r;
        g_cursor[idx] = r;
    }
}

// ---------------- scatter edges into CSR ------------------------------------
__global__ void k_scatter(const int* __restrict__ ei) {
    int e = blockIdx.x * blockDim.x + threadIdx.x;
    if (e < N_EDGES) {
        int s = ei[e];
        int d = ei[N_EDGES + e];
        int pos = atomicAdd(&g_cursor[d], 1);
        g_esrc[pos] = s;
    }
}

// ---------------- GEMM1: hs1 = (x @ W1) * dinv  -> fp16 ----------------------
// thread (g = t&3, row pair): cols [16g..16g+15] as 4 float4 + scalar col 64+g.
__global__ __launch_bounds__(256) void k_gemm1(const float* __restrict__ x,
                                               const float* __restrict__ W1) {
    __shared__ float Ws[D_IN * H1P];   // 100x68, pad cols zero (27.2 KB)
    __shared__ float xs[128 * 25];     // 12.8 KB
    int t = threadIdx.x;

    for (int idx = t; idx < D_IN * H1P; idx += 256) {
        int k = idx / H1P, c = idx % H1P;
        Ws[idx] = (c < D_H1) ? W1[k * D_H1 + c] : 0.0f;
    }

    int g     = t & 3;
    int rp    = (t >> 2) * 2;
    int rbase = blockIdx.x * 128;

    float4 a0[4], a1[4];
    float  e0 = 0.0f, e1 = 0.0f;
#pragma unroll
    for (int j = 0; j < 4; j++) {
        a0[j] = make_float4(0.f, 0.f, 0.f, 0.f);
        a1[j] = make_float4(0.f, 0.f, 0.f, 0.f);
    }

    for (int kc = 0; kc < 4; kc++) {
        __syncthreads();
        for (int idx = t; idx < 128 * 25; idx += 256) {
            int rr = idx / 25, kk = idx % 25;
            int r = rbase + rr;
            xs[idx] = (r < N_NODES) ? x[r * D_IN + kc * 25 + kk] : 0.0f;
        }
        __syncthreads();
        for (int kk = 0; kk < 25; kk++) {
            float xv0 = xs[rp * 25 + kk];
            float xv1 = xs[rp * 25 + 25 + kk];
            const float* wrow = &Ws[(kc * 25 + kk) * H1P];
            const float4* wr = (const float4*)(wrow + 16 * g);
            float wsc = wrow[64 + g];
#pragma unroll
            for (int j = 0; j < 4; j++) {
                float4 w = wr[j];
                a0[j].x += xv0 * w.x; a0[j].y += xv0 * w.y;
                a0[j].z += xv0 * w.z; a0[j].w += xv0 * w.w;
                a1[j].x += xv1 * w.x; a1[j].y += xv1 * w.y;
                a1[j].z += xv1 * w.z; a1[j].w += xv1 * w.w;
            }
            e0 += xv0 * wsc;
            e1 += xv1 * wsc;
        }
    }

    __half* hs = (__half*)g_h1h;
    const __half hz = __float2half_rn(0.0f);
#pragma unroll
    for (int rr = 0; rr < 2; rr++) {
        int r = rbase + rp + rr;
        if (r >= N_NODES) break;
        float d = g_dinv[r];
        float4* av = rr ? a1 : a0;
        float   ev = rr ? e1 : e0;
        uint4 u0, u1;
        __half2* hp0 = (__half2*)&u0;
        __half2* hp1 = (__half2*)&u1;
        hp0[0] = __floats2half2_rn(av[0].x * d, av[0].y * d);
        hp0[1] = __floats2half2_rn(av[0].z * d, av[0].w * d);
        hp0[2] = __floats2half2_rn(av[1].x * d, av[1].y * d);
        hp0[3] = __floats2half2_rn(av[1].z * d, av[1].w * d);
        hp1[0] = __floats2half2_rn(av[2].x * d, av[2].y * d);
        hp1[1] = __floats2half2_rn(av[2].z * d, av[2].w * d);
        hp1[2] = __floats2half2_rn(av[3].x * d, av[3].y * d);
        hp1[3] = __floats2half2_rn(av[3].z * d, av[3].w * d);
        uint4* dst = (uint4*)(hs + (unsigned)r * H1H + 16 * g);
        dst[0] = u0;
        dst[1] = u1;
        hs[(unsigned)r * H1H + 64 + g] = __float2half_rn(ev * d);
        hs[(unsigned)r * H1H + 68 + g] = hz;   // zero pad 68..71
    }
}

// ---------------- fp16 chunk accumulate --------------------------------------
__device__ __forceinline__ void acc_chunk(float* a, uint4 q) {
    const __half2* hp = (const __half2*)&q;
#pragma unroll
    for (int j = 0; j < 4; j++) {
        float2 f = __half22float2(hp[j]);
        a[2 * j]     += f.x;
        a[2 * j + 1] += f.y;
    }
}

// ------- fused agg1 + GEMM2:  hs2 = (relu(dinv*(Σ hs1) + b1) @ W2) * dinv ----
// Phase 1: 288 threads, 9 chunk-threads per node, 32 nodes/block -> smem rows.
// Phase 2: 256 threads, 8 threads per node, 8 output cols each -> fp16 h2.
__global__ __launch_bounds__(288) void k_agg1g2(const float* __restrict__ b1,
                                                const float* __restrict__ W2) {
    __shared__ float W2s[D_H1 * D_H2];   // 16.6 KB
    __shared__ float b1s[D_H1];
    __shared__ float xsm[32][66];        // 8.4 KB, cols 0..64 used
    int t = threadIdx.x;

    for (int idx = t; idx < D_H1 * D_H2; idx += 288) W2s[idx] = W2[idx];
    if (t < D_H1) b1s[t] = b1[t];

    int ln = t / 9;
    int c  = t - ln * 9;
    int i  = blockIdx.x * 32 + ln;       // N_NODES = 6250*32 exactly

    const uint4* hs = (const uint4*)g_h1h;      // N x 9 chunks
    int beg = __ldg(&g_rowptr[i]);
    int end = __ldg(&g_rowptr[i + 1]);

    float a[8] = {0, 0, 0, 0, 0, 0, 0, 0};
    acc_chunk(a, __ldg(&hs[(unsigned)i * 9 + c]));      // self loop

    int k = beg;
    for (; k + 3 < end; k += 4) {
        int s0 = __ldg(&g_esrc[k]);
        int s1 = __ldg(&g_esrc[k + 1]);
        int s2 = __ldg(&g_esrc[k + 2]);
        int s3 = __ldg(&g_esrc[k + 3]);
        uint4 q0 = __ldg(&hs[(unsigned)s0 * 9 + c]);
        uint4 q1 = __ldg(&hs[(unsigned)s1 * 9 + c]);
        uint4 q2 = __ldg(&hs[(unsigned)s2 * 9 + c]);
        uint4 q3 = __ldg(&hs[(unsigned)s3 * 9 + c]);
        acc_chunk(a, q0); acc_chunk(a, q1); acc_chunk(a, q2); acc_chunk(a, q3);
    }
    for (; k < end; k++) {
        int s = __ldg(&g_esrc[k]);
        acc_chunk(a, __ldg(&hs[(unsigned)s * 9 + c]));
    }

    {   // relu(dinv * agg + b1) -> smem row
        float d = __ldg(&g_dinv[i]);
#pragma unroll
        for (int j = 0; j < 8; j++) {
            int col = 8 * c + j;
            if (col < D_H1)
                xsm[ln][col] = fmaxf(d * a[j] + b1s[col], 0.0f);
        }
    }
    __syncthreads();

    // Phase 2: in-block GEMM 32x65 @ 65x64
    if (t < 256) {
        int n2 = t >> 3;
        int c8 = t & 7;                  // cols 8c8 .. 8c8+7
        float4 s0 = make_float4(0.f, 0.f, 0.f, 0.f);
        float4 s1 = make_float4(0.f, 0.f, 0.f, 0.f);
        for (int kk = 0; kk < D_H1; kk++) {
            float xv = xsm[n2][kk];
            const float4* w = (const float4*)&W2s[kk * D_H2 + 8 * c8];
            float4 w0 = w[0], w1 = w[1];
            s0.x += xv * w0.x; s0.y += xv * w0.y;
            s0.z += xv * w0.z; s0.w += xv * w0.w;
            s1.x += xv * w1.x; s1.y += xv * w1.y;
            s1.z += xv * w1.z; s1.w += xv * w1.w;
        }
        int gi = blockIdx.x * 32 + n2;
        float dd = __ldg(&g_dinv[gi]);
        uint4 u;
        __half2* hp = (__half2*)&u;
        hp[0] = __floats2half2_rn(s0.x * dd, s0.y * dd);
        hp[1] = __floats2half2_rn(s0.z * dd, s0.w * dd);
        hp[2] = __floats2half2_rn(s1.x * dd, s1.y * dd);
        hp[3] = __floats2half2_rn(s1.z * dd, s1.w * dd);
        *(uint4*)((__half*)g_h2h + (unsigned)gi * D_H2 + 8 * c8) = u;
    }
}

// ------- agg2 + output fused: out[i]=relu(sum_c relu(agg2_c+b2)*Wout + bout) -
// 8 chunk-threads per node, 32 nodes per 256-thread block.
__global__ __launch_bounds__(256) void k_agg2out(const float* __restrict__ b2,
                                                 const float* __restrict__ Wout,
                                                 const float* __restrict__ bout,
                                                 float* __restrict__ out) {
    int t  = threadIdx.x;
    int ln = t >> 3;
    int c  = t & 7;
    int i  = blockIdx.x * 32 + ln;
    if (i >= N_NODES) return;

    const uint4* hs = (const uint4*)g_h2h;      // N x 8 chunks
    int beg = __ldg(&g_rowptr[i]);
    int end = __ldg(&g_rowptr[i + 1]);

    float a[8] = {0, 0, 0, 0, 0, 0, 0, 0};
    acc_chunk(a, __ldg(&hs[(unsigned)i * 8 + c]));      // self loop

    int k = beg;
    for (; k + 3 < end; k += 4) {
        int s0 = __ldg(&g_esrc[k]);
        int s1 = __ldg(&g_esrc[k + 1]);
        int s2 = __ldg(&g_esrc[k + 2]);
        int s3 = __ldg(&g_esrc[k + 3]);
        uint4 q0 = __ldg(&hs[(unsigned)s0 * 8 + c]);
        uint4 q1 = __ldg(&hs[(unsigned)s1 * 8 + c]);
        uint4 q2 = __ldg(&hs[(unsigned)s2 * 8 + c]);
        uint4 q3 = __ldg(&hs[(unsigned)s3 * 8 + c]);
        acc_chunk(a, q0); acc_chunk(a, q1); acc_chunk(a, q2); acc_chunk(a, q3);
    }
    for (; k < end; k++) {
        int s = __ldg(&g_esrc[k]);
        acc_chunk(a, __ldg(&hs[(unsigned)s * 8 + c]));
    }

    float d = __ldg(&g_dinv[i]);
    float4 b2a = __ldg((const float4*)b2 + c * 2);
    float4 b2b = __ldg((const float4*)b2 + c * 2 + 1);
    float4 woa = __ldg((const float4*)Wout + c * 2);
    float4 wob = __ldg((const float4*)Wout + c * 2 + 1);

    float s = fmaxf(d * a[0] + b2a.x, 0.0f) * woa.x
            + fmaxf(d * a[1] + b2a.y, 0.0f) * woa.y
            + fmaxf(d * a[2] + b2a.z, 0.0f) * woa.z
            + fmaxf(d * a[3] + b2a.w, 0.0f) * woa.w
            + fmaxf(d * a[4] + b2b.x, 0.0f) * wob.x
            + fmaxf(d * a[5] + b2b.y, 0.0f) * wob.y
            + fmaxf(d * a[6] + b2b.z, 0.0f) * wob.z
            + fmaxf(d * a[7] + b2b.w, 0.0f) * wob.w;

    s += __shfl_xor_sync(0xffffffffu, s, 1);
    s += __shfl_xor_sync(0xffffffffu, s, 2);
    s += __shfl_xor_sync(0xffffffffu, s, 4);
    if (c == 0) out[i] = fmaxf(s + __ldg(bout), 0.0f);
}

// ---------------- launch ----------------------------------------------------
extern "C" void kernel_launch(void* const* d_in, const int* in_sizes, int n_in,
                              void* d_out, int out_size) {
    const float* x    = (const float*)d_in[0];
    const int*   ei   = (const int*)  d_in[1];
    const float* W1   = (const float*)d_in[2];
    const float* b1   = (const float*)d_in[3];
    const float* W2   = (const float*)d_in[4];
    const float* b2   = (const float*)d_in[5];
    const float* Wout = (const float*)d_in[6];
    const float* bout = (const float*)d_in[7];
    float* out = (float*)d_out;

    const int NB_N = (N_NODES + 255) / 256;
    const int NB_E = (N_EDGES + 255) / 256;
    const int NB_G = (N_NODES + 127) / 128;
    const int NB_A = (N_NODES + 31) / 32;    // 6250

    k_deg_zero <<<NB_N, 256>>>();
    k_deg_count<<<NB_E, 256>>>(ei);
    k_dinv     <<<NB_N, 256>>>();
    k_gemm1    <<<NB_G, 256>>>(x, W1);       // launch #3 -> ncu window
    k_scan1    <<<SCAN_NB, SCAN_B>>>();
    k_scan2    <<<1, 256>>>();
    k_scan3    <<<SCAN_NB, SCAN_B>>>();
    k_scatter  <<<NB_E, 256>>>(ei);
    k_agg1g2   <<<NB_A, 288>>>(b1, W2);
    k_agg2out  <<<NB_A, 256>>>(b2, Wout, bout, out);
}

// round 8
// speedup vs baseline: 1.2087x; 1.2087x over previous
#include <cuda_runtime.h>
#include <cuda_fp16.h>

#define N_NODES 200000
#define N_EDGES 6400000
#define D_IN    100
#define D_H1    65
#define H1P     68      // fp32 compute pad (17 float4)
#define H1H     72      // fp16 row pad: 9 x uint4 (8 halves each) = 144B
#define D_H2    64      // fp16 row: 8 x uint4 = 128B

#define SCAN_B  1024
#define SCAN_NB ((N_NODES + SCAN_B - 1) / SCAN_B)   // 196

// ---------------- scratch (device globals; no allocation allowed) -----------
__device__ uint4  g_h1h [(N_NODES * H1H) / 8];   // 28.8 MB  fp16 h1*dinv (L2-resident)
__device__ uint4  g_h2h [(N_NODES * D_H2) / 8];  // 25.6 MB  fp16 h2*dinv (L2-resident)
__device__ float4 g_agg1[(N_NODES * H1H) / 4];   // 57.6 MB  fp32 layer-1 aggregate
__device__ float  g_dinv[N_NODES];
__device__ int    g_deg [N_NODES];
__device__ int    g_rowptr[N_NODES + 1];
__device__ int    g_cursor[N_NODES];
__device__ int    g_esrc[N_EDGES];               // CSR: src ids grouped by dst
__device__ int    g_bsum[SCAN_NB];               // per-block scan totals

// ---------------- degree / dinv ---------------------------------------------
__global__ void k_deg_zero() {
    int i = blockIdx.x * blockDim.x + threadIdx.x;
    if (i < N_NODES) g_deg[i] = 0;
}

__global__ void k_deg_count(const int* __restrict__ ei) {
    int e = blockIdx.x * blockDim.x + threadIdx.x;
    if (e < N_EDGES) atomicAdd(&g_deg[ei[N_EDGES + e]], 1);   // dst = ei[1]
}

__global__ void k_dinv() {
    int i = blockIdx.x * blockDim.x + threadIdx.x;
    if (i < N_NODES) g_dinv[i] = rsqrtf((float)(g_deg[i] + 1));  // +1 self loop
}

// ---------------- GEMM1: hs1 = (x @ W1) * dinv  -> fp16 ----------------------
// 4 rows x 17 cols per thread: 68 FMA vs 21 LDS per k-step (3.2:1).
// k-chunks of 20 so smem = 27.2 + 20.0 = 47.2 KB < 48 KB static limit.
__global__ __launch_bounds__(256, 2) void k_gemm1(const float* __restrict__ x,
                                                  const float* __restrict__ W1) {
    __shared__ float Ws[D_IN * H1P];   // 100x68, pad cols zero (27.2 KB)
    __shared__ float xs[256 * 20];     // 20.0 KB
    int t = threadIdx.x;

    for (int idx = t; idx < D_IN * H1P; idx += 256) {
        int k = idx / H1P, c = idx % H1P;
        Ws[idx] = (c < D_H1) ? W1[k * D_H1 + c] : 0.0f;
    }

    int g     = t & 3;
    int rq    = t >> 2;                 // 64 row-quads per block
    int rbase = blockIdx.x * 256;

    float acc[4][17];
#pragma unroll
    for (int r = 0; r < 4; r++)
#pragma unroll
        for (int j = 0; j < 17; j++) acc[r][j] = 0.0f;

    for (int kc = 0; kc < 5; kc++) {               // k chunks of 20
        __syncthreads();
        for (int idx = t; idx < 256 * 20; idx += 256) {
            int rr = idx / 20, kk = idx % 20;
            int r = rbase + rr;
            xs[idx] = (r < N_NODES) ? x[r * D_IN + kc * 20 + kk] : 0.0f;
        }
        __syncthreads();
        const float* xrow = &xs[rq * 4 * 20];
        for (int kk = 0; kk < 20; kk++) {
            float xv0 = xrow[kk];
            float xv1 = xrow[20 + kk];
            float xv2 = xrow[40 + kk];
            float xv3 = xrow[60 + kk];
            const float* wr = &Ws[(kc * 20 + kk) * H1P + g];
#pragma unroll
            for (int j = 0; j < 17; j++) {
                float w = wr[4 * j];
                acc[0][j] += xv0 * w;
                acc[1][j] += xv1 * w;
                acc[2][j] += xv2 * w;
                acc[3][j] += xv3 * w;
            }
        }
    }

    __half* hs = (__half*)g_h1h;
    const __half hz = __float2half_rn(0.0f);
#pragma unroll
    for (int r = 0; r < 4; r++) {
        int row = rbase + rq * 4 + r;
        if (row < N_NODES) {
            float d = g_dinv[row];
            __half* hrow = hs + (unsigned)row * H1H;
#pragma unroll
            for (int j = 0; j < 17; j++)
                hrow[g + 4 * j] = __float2half_rn(acc[r][j] * d);
            hrow[68 + g] = hz;   // zero pad 68..71
        }
    }
}

// ---------------- scan pass 1: per-block exclusive scan ----------------------
__global__ __launch_bounds__(SCAN_B) void k_scan1() {
    __shared__ int wsum[32];
    int t = threadIdx.x, lane = t & 31, wid = t >> 5;
    int idx = blockIdx.x * SCAN_B + t;
    int v = (idx < N_NODES) ? g_deg[idx] : 0;
    int x = v;
#pragma unroll
    for (int off = 1; off < 32; off <<= 1) {
        int n = __shfl_up_sync(0xffffffffu, x, off);
        if (lane >= off) x += n;
    }
    if (lane == 31) wsum[wid] = x;
    __syncthreads();
    if (wid == 0) {
        int w = wsum[lane];
#pragma unroll
        for (int off = 1; off < 32; off <<= 1) {
            int n = __shfl_up_sync(0xffffffffu, w, off);
            if (lane >= off) w += n;
        }
        wsum[lane] = w;   // inclusive warp totals
    }
    __syncthreads();
    int warpoff = (wid > 0) ? wsum[wid - 1] : 0;
    int excl = x - v + warpoff;                    // block-local exclusive
    if (idx < N_NODES) g_rowptr[idx] = excl;
    if (t == SCAN_B - 1) g_bsum[blockIdx.x] = warpoff + x;   // block total
}

// ---------------- scan pass 2: scan the 196 block totals (1 tiny block) -----
__global__ __launch_bounds__(256) void k_scan2() {
    __shared__ int wsum[8];
    int t = threadIdx.x, lane = t & 31, wid = t >> 5;
    int v = (t < SCAN_NB) ? g_bsum[t] : 0;
    int x = v;
#pragma unroll
    for (int off = 1; off < 32; off <<= 1) {
        int n = __shfl_up_sync(0xffffffffu, x, off);
        if (lane >= off) x += n;
    }
    if (lane == 31) wsum[wid] = x;
    __syncthreads();
    if (wid == 0 && lane < 8) {
        int w = wsum[lane];
#pragma unroll
        for (int off = 1; off < 8; off <<= 1) {
            int n = __shfl_up_sync(0xffu, w, off);
            if (lane >= off) w += n;
        }
        wsum[lane] = w;
    }
    __syncthreads();
    int warpoff = (wid > 0) ? wsum[wid - 1] : 0;
    int excl = x - v + warpoff;
    if (t < SCAN_NB) g_bsum[t] = excl;
    if (t == SCAN_NB - 1) g_rowptr[N_NODES] = excl + v;   // grand total
}

// ---------------- scan pass 3: add block offsets, init cursor ----------------
__global__ __launch_bounds__(SCAN_B) void k_scan3() {
    int idx = blockIdx.x * SCAN_B + threadIdx.x;
    if (idx < N_NODES) {
        int r = g_rowptr[idx] + g_bsum[blockIdx.x];
        g_rowptr[idx] = r;
        g_cursor[idx] = r;
    }
}

// ---------------- scatter edges into CSR ------------------------------------
__global__ void k_scatter(const int* __restrict__ ei) {
    int e = blockIdx.x * blockDim.x + threadIdx.x;
    if (e < N_EDGES) {
        int s = ei[e];
        int d = ei[N_EDGES + e];
        int pos = atomicAdd(&g_cursor[d], 1);
        g_esrc[pos] = s;
    }
}

// ---------------- fp16 chunk accumulate --------------------------------------
__device__ __forceinline__ void acc_chunk(float* a, uint4 q) {
    const __half2* hp = (const __half2*)&q;
#pragma unroll
    for (int j = 0; j < 4; j++) {
        float2 f = __half22float2(hp[j]);
        a[2 * j]     += f.x;
        a[2 * j + 1] += f.y;
    }
}

// ---------------- agg1: agg1[i] = dinv[i] * (hs1[i] + sum hs1[src]) ---------
// 9 chunk-threads per node, 32 nodes per 288-thread block.
__global__ __launch_bounds__(288) void k_agg1() {
    int t  = threadIdx.x;
    int ln = t / 9;
    int c  = t - ln * 9;
    int i  = blockIdx.x * 32 + ln;
    if (i >= N_NODES) return;

    const uint4* hs = (const uint4*)g_h1h;      // N x 9 chunks
    int beg = __ldg(&g_rowptr[i]);
    int end = __ldg(&g_rowptr[i + 1]);

    float a[8] = {0, 0, 0, 0, 0, 0, 0, 0};
    acc_chunk(a, __ldg(&hs[(unsigned)i * 9 + c]));      // self loop

    int k = beg;
    for (; k + 3 < end; k += 4) {
        int s0 = __ldg(&g_esrc[k]);
        int s1 = __ldg(&g_esrc[k + 1]);
        int s2 = __ldg(&g_esrc[k + 2]);
        int s3 = __ldg(&g_esrc[k + 3]);
        uint4 q0 = __ldg(&hs[(unsigned)s0 * 9 + c]);
        uint4 q1 = __ldg(&hs[(unsigned)s1 * 9 + c]);
        uint4 q2 = __ldg(&hs[(unsigned)s2 * 9 + c]);
        uint4 q3 = __ldg(&hs[(unsigned)s3 * 9 + c]);
        acc_chunk(a, q0); acc_chunk(a, q1); acc_chunk(a, q2); acc_chunk(a, q3);
    }
    for (; k < end; k++) {
        int s = __ldg(&g_esrc[k]);
        acc_chunk(a, __ldg(&hs[(unsigned)s * 9 + c]));
    }

    float d = __ldg(&g_dinv[i]);
    float4 o0 = make_float4(d * a[0], d * a[1], d * a[2], d * a[3]);
    float4 o1 = make_float4(d * a[4], d * a[5], d * a[6], d * a[7]);
    g_agg1[(unsigned)i * 18 + c * 2]     = o0;
    g_agg1[(unsigned)i * 18 + c * 2 + 1] = o1;
}

// ---------------- GEMM2: hs2 = (relu(agg1 + b1) @ W2) * dinv -> fp16 --------
__global__ __launch_bounds__(256) void k_gemm2(const float* __restrict__ W2,
                                               const float* __restrict__ b1) {
    __shared__ float Ws[D_H1 * D_H2];  // 65x64 (16.6 KB)
    __shared__ float xs[128 * 33];     // stride 33
    const float* a1f = (const float*)g_agg1;
    int t = threadIdx.x;

    for (int idx = t; idx < D_H1 * D_H2; idx += 256) Ws[idx] = W2[idx];

    int g     = t & 3;
    int rp    = (t >> 2) * 2;
    int rbase = blockIdx.x * 128;

    float acc0[16], acc1[16];
#pragma unroll
    for (int j = 0; j < 16; j++) { acc0[j] = 0.0f; acc1[j] = 0.0f; }

    int k0 = 0;
    for (int kc = 0; kc < 2; kc++) {
        int len = kc ? 32 : 33;
        __syncthreads();
        for (int idx = t; idx < 128 * len; idx += 256) {
            int rr = idx / len, kk = idx % len;
            int r = rbase + rr, k = k0 + kk;
            xs[rr * 33 + kk] =
                (r < N_NODES) ? fmaxf(a1f[(unsigned)r * H1H + k] + b1[k], 0.0f) : 0.0f;
        }
        __syncthreads();
        for (int kk = 0; kk < len; kk++) {
            float xv0 = xs[rp * 33 + kk];
            float xv1 = xs[(rp + 1) * 33 + kk];
            const float* wr = &Ws[(k0 + kk) * D_H2 + g];
#pragma unroll
            for (int j = 0; j < 16; j++) {
                float w = wr[4 * j];
                acc0[j] += xv0 * w;
                acc1[j] += xv1 * w;
            }
        }
        k0 += len;
    }

    __half* hs = (__half*)g_h2h;
    int r0 = rbase + rp;
    if (r0 < N_NODES) {
        float d = g_dinv[r0];
#pragma unroll
        for (int j = 0; j < 16; j++)
            hs[r0 * D_H2 + g + 4 * j] = __float2half_rn(acc0[j] * d);
    }
    int r1 = r0 + 1;
    if (r1 < N_NODES) {
        float d = g_dinv[r1];
#pragma unroll
        for (int j = 0; j < 16; j++)
            hs[r1 * D_H2 + g + 4 * j] = __float2half_rn(acc1[j] * d);
    }
}

// ------- agg2 + output fused: out[i]=relu(sum_c relu(agg2_c+b2)*Wout + bout) -
// 8 chunk-threads per node, 32 nodes per 256-thread block.
__global__ __launch_bounds__(256) void k_agg2out(const float* __restrict__ b2,
                                                 const float* __restrict__ Wout,
                                                 const float* __restrict__ bout,
                                                 float* __restrict__ out) {
    int t  = threadIdx.x;
    int ln = t >> 3;
    int c  = t & 7;
    int i  = blockIdx.x * 32 + ln;
    if (i >= N_NODES) return;

    const uint4* hs = (const uint4*)g_h2h;      // N x 8 chunks
    int beg = __ldg(&g_rowptr[i]);
    int end = __ldg(&g_rowptr[i + 1]);

    float a[8] = {0, 0, 0, 0, 0, 0, 0, 0};
    acc_chunk(a, __ldg(&hs[(unsigned)i * 8 + c]));      // self loop

    int k = beg;
    for (; k + 3 < end; k += 4) {
        int s0 = __ldg(&g_esrc[k]);
        int s1 = __ldg(&g_esrc[k + 1]);
        int s2 = __ldg(&g_esrc[k + 2]);
        int s3 = __ldg(&g_esrc[k + 3]);
        uint4 q0 = __ldg(&hs[(unsigned)s0 * 8 + c]);
        uint4 q1 = __ldg(&hs[(unsigned)s1 * 8 + c]);
        uint4 q2 = __ldg(&hs[(unsigned)s2 * 8 + c]);
        uint4 q3 = __ldg(&hs[(unsigned)s3 * 8 + c]);
        acc_chunk(a, q0); acc_chunk(a, q1); acc_chunk(a, q2); acc_chunk(a, q3);
    }
    for (; k < end; k++) {
        int s = __ldg(&g_esrc[k]);
        acc_chunk(a, __ldg(&hs[(unsigned)s * 8 + c]));
    }

    float d = __ldg(&g_dinv[i]);
    float4 b2a = __ldg((const float4*)b2 + c * 2);
    float4 b2b = __ldg((const float4*)b2 + c * 2 + 1);
    float4 woa = __ldg((const float4*)Wout + c * 2);
    float4 wob = __ldg((const float4*)Wout + c * 2 + 1);

    float s = fmaxf(d * a[0] + b2a.x, 0.0f) * woa.x
            + fmaxf(d * a[1] + b2a.y, 0.0f) * woa.y
            + fmaxf(d * a[2] + b2a.z, 0.0f) * woa.z
            + fmaxf(d * a[3] + b2a.w, 0.0f) * woa.w
            + fmaxf(d * a[4] + b2b.x, 0.0f) * wob.x
            + fmaxf(d * a[5] + b2b.y, 0.0f) * wob.y
            + fmaxf(d * a[6] + b2b.z, 0.0f) * wob.z
            + fmaxf(d * a[7] + b2b.w, 0.0f) * wob.w;

    s += __shfl_xor_sync(0xffffffffu, s, 1);
    s += __shfl_xor_sync(0xffffffffu, s, 2);
    s += __shfl_xor_sync(0xffffffffu, s, 4);
    if (c == 0) out[i] = fmaxf(s + __ldg(bout), 0.0f);
}

// ---------------- launch ----------------------------------------------------
extern "C" void kernel_launch(void* const* d_in, const int* in_sizes, int n_in,
                              void* d_out, int out_size) {
    const float* x    = (const float*)d_in[0];
    const int*   ei   = (const int*)  d_in[1];
    const float* W1   = (const float*)d_in[2];
    const float* b1   = (const float*)d_in[3];
    const float* W2   = (const float*)d_in[4];
    const float* b2   = (const float*)d_in[5];
    const float* Wout = (const float*)d_in[6];
    const float* bout = (const float*)d_in[7];
    float* out = (float*)d_out;

    const int NB_N = (N_NODES + 255) / 256;
    const int NB_E = (N_EDGES + 255) / 256;
    const int NB_G1 = (N_NODES + 255) / 256;   // 782, 256 rows/block
    const int NB_G2 = (N_NODES + 127) / 128;
    const int NB_A = (N_NODES + 31) / 32;      // 6250

    k_deg_zero <<<NB_N, 256>>>();
    k_deg_count<<<NB_E, 256>>>(ei);
    k_dinv     <<<NB_N, 256>>>();
    k_gemm1    <<<NB_G1, 256>>>(x, W1);        // launch #3 -> ncu window
    k_scan1    <<<SCAN_NB, SCAN_B>>>();
    k_scan2    <<<1, 256>>>();
    k_scan3    <<<SCAN_NB, SCAN_B>>>();
    k_scatter  <<<NB_E, 256>>>(ei);
    k_agg1     <<<NB_A, 288>>>();
    k_gemm2    <<<NB_G2, 256>>>(W2, b1);
    k_agg2out  <<<NB_A, 256>>>(b2, Wout, bout, out);
}

// round 9
// speedup vs baseline: 1.5250x; 1.2617x over previous
#include <cuda_runtime.h>
#include <cuda_fp16.h>

#define N_NODES 200000
#define N_EDGES 6400000
#define D_IN    100
#define D_H1    65
#define H1H     72      // fp16 row pad: 9 x uint4 (8 halves each) = 144B
#define D_H2    64      // fp16 row: 8 x uint4 = 128B

#define SCAN_B  1024
#define SCAN_NB ((N_NODES + SCAN_B - 1) / SCAN_B)   // 196

// ---------------- scratch (device globals; no allocation allowed) -----------
__device__ uint4  g_h1h [(N_NODES * H1H) / 8];   // 28.8 MB  fp16 h1*dinv (L2-resident)
__device__ uint4  g_h2h [(N_NODES * D_H2) / 8];  // 25.6 MB  fp16 h2*dinv (L2-resident)
__device__ float4 g_agg1[(N_NODES * H1H) / 4];   // 57.6 MB  fp32 layer-1 aggregate
__device__ float  g_dinv[N_NODES];
__device__ int    g_deg [N_NODES];
__device__ int    g_rowptr[N_NODES + 1];
__device__ int    g_cursor[N_NODES];
__device__ int    g_esrc[N_EDGES];               // CSR: src ids grouped by dst
__device__ int    g_bsum[SCAN_NB];               // per-block scan totals

// ---------------- degree / dinv ---------------------------------------------
__global__ void k_deg_zero() {
    int i = blockIdx.x * blockDim.x + threadIdx.x;
    if (i < N_NODES) g_deg[i] = 0;
}

__global__ void k_deg_count(const int* __restrict__ ei) {
    int e = blockIdx.x * blockDim.x + threadIdx.x;
    if (e < N_EDGES) atomicAdd(&g_deg[ei[N_EDGES + e]], 1);   // dst = ei[1]
}

__global__ void k_dinv() {
    int i = blockIdx.x * blockDim.x + threadIdx.x;
    if (i < N_NODES) g_dinv[i] = rsqrtf((float)(g_deg[i] + 1));  // +1 self loop
}

// ---------------- GEMM1 (tensor core): hs1 = (x @ W1) * dinv -> fp16 --------
// mma.m16n8k16 f16->f32. 8 warps x 16 rows = 128 rows/block.
// K: 100 -> 112 (7 k-steps). N: 65 -> 72 (9 n-tiles; cols 65..71 zero via W pad).
#define XS_STRIDE 57    // half2 words per row (56 data + 1 pad, odd => few conflicts)
__global__ __launch_bounds__(256) void k_gemm1(const float* __restrict__ x,
                                               const float* __restrict__ W1) {
    __shared__ __half2 Xs[128 * XS_STRIDE];  // 29.2 KB
    __shared__ __half2 Wsm[56 * 72];         // 16.1 KB  (k-pair, n)
    int t = threadIdx.x;
    int rbase = blockIdx.x * 128;

    // W1 [100][65] fp32 -> Wsm[kp][n] = (W[2kp][n], W[2kp+1][n]), zero-padded
    for (int idx = t; idx < 56 * 72; idx += 256) {
        int kp = idx / 72, n = idx % 72;
        int k0 = 2 * kp;
        float lo = (k0 < D_IN && n < D_H1) ? W1[k0 * D_H1 + n] : 0.0f;
        float hi = (k0 + 1 < D_IN && n < D_H1) ? W1[(k0 + 1) * D_H1 + n] : 0.0f;
        Wsm[idx] = __floats2half2_rn(lo, hi);
    }

    // x rows -> fp16 k-packed
    for (int idx = t; idx < 128 * 56; idx += 256) {
        int rr = idx / 56, kp = idx % 56;
        int row = rbase + rr;
        __half2 v = __floats2half2_rn(0.0f, 0.0f);
        if (row < N_NODES && kp < 50) {
            float2 f2 = *(const float2*)(x + (size_t)row * D_IN + 2 * kp);
            v = __floats2half2_rn(f2.x, f2.y);
        }
        Xs[rr * XS_STRIDE + kp] = v;
    }
    __syncthreads();

    int w    = t >> 5;           // warp id: rows [w*16, w*16+16)
    int lane = t & 31;
    int g    = lane >> 2;        // group 0..7
    int tig  = lane & 3;         // thread-in-group 0..3
    int m0   = w * 16;

    float acc[9][4];
#pragma unroll
    for (int nt = 0; nt < 9; nt++)
#pragma unroll
        for (int j = 0; j < 4; j++) acc[nt][j] = 0.0f;

    const unsigned* XsU = (const unsigned*)Xs;
    const unsigned* WsU = (const unsigned*)Wsm;

#pragma unroll
    for (int ks = 0; ks < 7; ks++) {
        int kb = ks * 8;
        unsigned a0 = XsU[(m0 + g)     * XS_STRIDE + kb + tig];
        unsigned a1 = XsU[(m0 + g + 8) * XS_STRIDE + kb + tig];
        unsigned a2 = XsU[(m0 + g)     * XS_STRIDE + kb + 4 + tig];
        unsigned a3 = XsU[(m0 + g + 8) * XS_STRIDE + kb + 4 + tig];
#pragma unroll
        for (int nt = 0; nt < 9; nt++) {
            unsigned b0 = WsU[(kb + tig)     * 72 + nt * 8 + g];
            unsigned b1 = WsU[(kb + 4 + tig) * 72 + nt * 8 + g];
            asm volatile(
                "mma.sync.aligned.m16n8k16.row.col.f32.f16.f16.f32 "
                "{%0,%1,%2,%3}, {%4,%5,%6,%7}, {%8,%9}, {%0,%1,%2,%3};"
                : "+f"(acc[nt][0]), "+f"(acc[nt][1]),
                  "+f"(acc[nt][2]), "+f"(acc[nt][3])
                : "r"(a0), "r"(a1), "r"(a2), "r"(a3), "r"(b0), "r"(b1));
        }
    }

    // epilogue: c0,c1 -> row m0+g cols 2tig,2tig+1 ; c2,c3 -> row m0+g+8
    __half2* h2out = (__half2*)g_h1h;          // row stride 36 half2
    int row0 = rbase + m0 + g;
    int row1 = row0 + 8;
    float d0 = (row0 < N_NODES) ? g_dinv[row0] : 0.0f;
    float d1 = (row1 < N_NODES) ? g_dinv[row1] : 0.0f;
#pragma unroll
    for (int nt = 0; nt < 9; nt++) {
        int cw = nt * 4 + tig;                 // half2 col index
        if (row0 < N_NODES)
            h2out[(unsigned)row0 * 36 + cw] =
                __floats2half2_rn(acc[nt][0] * d0, acc[nt][1] * d0);
        if (row1 < N_NODES)
            h2out[(unsigned)row1 * 36 + cw] =
                __floats2half2_rn(acc[nt][2] * d1, acc[nt][3] * d1);
    }
}

// ---------------- scan pass 1: per-block exclusive scan ----------------------
__global__ __launch_bounds__(SCAN_B) void k_scan1() {
    __shared__ int wsum[32];
    int t = threadIdx.x, lane = t & 31, wid = t >> 5;
    int idx = blockIdx.x * SCAN_B + t;
    int v = (idx < N_NODES) ? g_deg[idx] : 0;
    int x = v;
#pragma unroll
    for (int off = 1; off < 32; off <<= 1) {
        int n = __shfl_up_sync(0xffffffffu, x, off);
        if (lane >= off) x += n;
    }
    if (lane == 31) wsum[wid] = x;
    __syncthreads();
    if (wid == 0) {
        int w = wsum[lane];
#pragma unroll
        for (int off = 1; off < 32; off <<= 1) {
            int n = __shfl_up_sync(0xffffffffu, w, off);
            if (lane >= off) w += n;
        }
        wsum[lane] = w;   // inclusive warp totals
    }
    __syncthreads();
    int warpoff = (wid > 0) ? wsum[wid - 1] : 0;
    int excl = x - v + warpoff;                    // block-local exclusive
    if (idx < N_NODES) g_rowptr[idx] = excl;
    if (t == SCAN_B - 1) g_bsum[blockIdx.x] = warpoff + x;   // block total
}

// ---------------- scan pass 2: scan the 196 block totals (1 tiny block) -----
__global__ __launch_bounds__(256) void k_scan2() {
    __shared__ int wsum[8];
    int t = threadIdx.x, lane = t & 31, wid = t >> 5;
    int v = (t < SCAN_NB) ? g_bsum[t] : 0;
    int x = v;
#pragma unroll
    for (int off = 1; off < 32; off <<= 1) {
        int n = __shfl_up_sync(0xffffffffu, x, off);
        if (lane >= off) x += n;
    }
    if (lane == 31) wsum[wid] = x;
    __syncthreads();
    if (wid == 0 && lane < 8) {
        int w = wsum[lane];
#pragma unroll
        for (int off = 1; off < 8; off <<= 1) {
            int n = __shfl_up_sync(0xffu, w, off);
            if (lane >= off) w += n;
        }
        wsum[lane] = w;
    }
    __syncthreads();
    int warpoff = (wid > 0) ? wsum[wid - 1] : 0;
    int excl = x - v + warpoff;
    if (t < SCAN_NB) g_bsum[t] = excl;
    if (t == SCAN_NB - 1) g_rowptr[N_NODES] = excl + v;   // grand total
}

// ---------------- scan pass 3: add block offsets, init cursor ----------------
__global__ __launch_bounds__(SCAN_B) void k_scan3() {
    int idx = blockIdx.x * SCAN_B + threadIdx.x;
    if (idx < N_NODES) {
        int r = g_rowptr[idx] + g_bsum[blockIdx.x];
        g_rowptr[idx] = r;
        g_cursor[idx] = r;
    }
}

// ---------------- scatter edges into CSR ------------------------------------
__global__ void k_scatter(const int* __restrict__ ei) {
    int e = blockIdx.x * blockDim.x + threadIdx.x;
    if (e < N_EDGES) {
        int s = ei[e];
        int d = ei[N_EDGES + e];
        int pos = atomicAdd(&g_cursor[d], 1);
        g_esrc[pos] = s;
    }
}

// ---------------- fp16 chunk accumulate --------------------------------------
__device__ __forceinline__ void acc_chunk(float* a, uint4 q) {
    const __half2* hp = (const __half2*)&q;
#pragma unroll
    for (int j = 0; j < 4; j++) {
        float2 f = __half22float2(hp[j]);
        a[2 * j]     += f.x;
        a[2 * j + 1] += f.y;
    }
}

// ---------------- agg1: agg1[i] = dinv[i] * (hs1[i] + sum hs1[src]) ---------
// 9 chunk-threads per node, 32 nodes per 288-thread block.
__global__ __launch_bounds__(288) void k_agg1() {
    int t  = threadIdx.x;
    int ln = t / 9;
    int c  = t - ln * 9;
    int i  = blockIdx.x * 32 + ln;
    if (i >= N_NODES) return;

    const uint4* hs = (const uint4*)g_h1h;      // N x 9 chunks
    int beg = __ldg(&g_rowptr[i]);
    int end = __ldg(&g_rowptr[i + 1]);

    float a[8] = {0, 0, 0, 0, 0, 0, 0, 0};
    acc_chunk(a, __ldg(&hs[(unsigned)i * 9 + c]));      // self loop

    int k = beg;
    for (; k + 3 < end; k += 4) {
        int s0 = __ldg(&g_esrc[k]);
        int s1 = __ldg(&g_esrc[k + 1]);
        int s2 = __ldg(&g_esrc[k + 2]);
        int s3 = __ldg(&g_esrc[k + 3]);
        uint4 q0 = __ldg(&hs[(unsigned)s0 * 9 + c]);
        uint4 q1 = __ldg(&hs[(unsigned)s1 * 9 + c]);
        uint4 q2 = __ldg(&hs[(unsigned)s2 * 9 + c]);
        uint4 q3 = __ldg(&hs[(unsigned)s3 * 9 + c]);
        acc_chunk(a, q0); acc_chunk(a, q1); acc_chunk(a, q2); acc_chunk(a, q3);
    }
    for (; k < end; k++) {
        int s = __ldg(&g_esrc[k]);
        acc_chunk(a, __ldg(&hs[(unsigned)s * 9 + c]));
    }

    float d = __ldg(&g_dinv[i]);
    float4 o0 = make_float4(d * a[0], d * a[1], d * a[2], d * a[3]);
    float4 o1 = make_float4(d * a[4], d * a[5], d * a[6], d * a[7]);
    g_agg1[(unsigned)i * 18 + c * 2]     = o0;
    g_agg1[(unsigned)i * 18 + c * 2 + 1] = o1;
}

// ---------------- GEMM2: hs2 = (relu(agg1 + b1) @ W2) * dinv -> fp16 --------
__global__ __launch_bounds__(256) void k_gemm2(const float* __restrict__ W2,
                                               const float* __restrict__ b1) {
    __shared__ float Ws[D_H1 * D_H2];  // 65x64 (16.6 KB)
    __shared__ float xs[128 * 33];     // stride 33
    const float* a1f = (const float*)g_agg1;
    int t = threadIdx.x;

    for (int idx = t; idx < D_H1 * D_H2; idx += 256) Ws[idx] = W2[idx];

    int g     = t & 3;
    int rp    = (t >> 2) * 2;
    int rbase = blockIdx.x * 128;

    float acc0[16], acc1[16];
#pragma unroll
    for (int j = 0; j < 16; j++) { acc0[j] = 0.0f; acc1[j] = 0.0f; }

    int k0 = 0;
    for (int kc = 0; kc < 2; kc++) {
        int len = kc ? 32 : 33;
        __syncthreads();
        for (int idx = t; idx < 128 * len; idx += 256) {
            int rr = idx / len, kk = idx % len;
            int r = rbase + rr, k = k0 + kk;
            xs[rr * 33 + kk] =
                (r < N_NODES) ? fmaxf(a1f[(unsigned)r * H1H + k] + b1[k], 0.0f) : 0.0f;
        }
        __syncthreads();
        for (int kk = 0; kk < len; kk++) {
            float xv0 = xs[rp * 33 + kk];
            float xv1 = xs[(rp + 1) * 33 + kk];
            const float* wr = &Ws[(k0 + kk) * D_H2 + g];
#pragma unroll
            for (int j = 0; j < 16; j++) {
                float w = wr[4 * j];
                acc0[j] += xv0 * w;
                acc1[j] += xv1 * w;
            }
        }
        k0 += len;
    }

    __half* hs = (__half*)g_h2h;
    int r0 = rbase + rp;
    if (r0 < N_NODES) {
        float d = g_dinv[r0];
#pragma unroll
        for (int j = 0; j < 16; j++)
            hs[r0 * D_H2 + g + 4 * j] = __float2half_rn(acc0[j] * d);
    }
    int r1 = r0 + 1;
    if (r1 < N_NODES) {
        float d = g_dinv[r1];
#pragma unroll
        for (int j = 0; j < 16; j++)
            hs[r1 * D_H2 + g + 4 * j] = __float2half_rn(acc1[j] * d);
    }
}

// ------- agg2 + output fused: out[i]=relu(sum_c relu(agg2_c+b2)*Wout + bout) -
// 8 chunk-threads per node, 32 nodes per 256-thread block.
__global__ __launch_bounds__(256) void k_agg2out(const float* __restrict__ b2,
                                                 const float* __restrict__ Wout,
                                                 const float* __restrict__ bout,
                                                 float* __restrict__ out) {
    int t  = threadIdx.x;
    int ln = t >> 3;
    int c  = t & 7;
    int i  = blockIdx.x * 32 + ln;
    if (i >= N_NODES) return;

    const uint4* hs = (const uint4*)g_h2h;      // N x 8 chunks
    int beg = __ldg(&g_rowptr[i]);
    int end = __ldg(&g_rowptr[i + 1]);

    float a[8] = {0, 0, 0, 0, 0, 0, 0, 0};
    acc_chunk(a, __ldg(&hs[(unsigned)i * 8 + c]));      // self loop

    int k = beg;
    for (; k + 3 < end; k += 4) {
        int s0 = __ldg(&g_esrc[k]);
        int s1 = __ldg(&g_esrc[k + 1]);
        int s2 = __ldg(&g_esrc[k + 2]);
        int s3 = __ldg(&g_esrc[k + 3]);
        uint4 q0 = __ldg(&hs[(unsigned)s0 * 8 + c]);
        uint4 q1 = __ldg(&hs[(unsigned)s1 * 8 + c]);
        uint4 q2 = __ldg(&hs[(unsigned)s2 * 8 + c]);
        uint4 q3 = __ldg(&hs[(unsigned)s3 * 8 + c]);
        acc_chunk(a, q0); acc_chunk(a, q1); acc_chunk(a, q2); acc_chunk(a, q3);
    }
    for (; k < end; k++) {
        int s = __ldg(&g_esrc[k]);
        acc_chunk(a, __ldg(&hs[(unsigned)s * 8 + c]));
    }

    float d = __ldg(&g_dinv[i]);
    float4 b2a = __ldg((const float4*)b2 + c * 2);
    float4 b2b = __ldg((const float4*)b2 + c * 2 + 1);
    float4 woa = __ldg((const float4*)Wout + c * 2);
    float4 wob = __ldg((const float4*)Wout + c * 2 + 1);

    float s = fmaxf(d * a[0] + b2a.x, 0.0f) * woa.x
            + fmaxf(d * a[1] + b2a.y, 0.0f) * woa.y
            + fmaxf(d * a[2] + b2a.z, 0.0f) * woa.z
            + fmaxf(d * a[3] + b2a.w, 0.0f) * woa.w
            + fmaxf(d * a[4] + b2b.x, 0.0f) * wob.x
            + fmaxf(d * a[5] + b2b.y, 0.0f) * wob.y
            + fmaxf(d * a[6] + b2b.z, 0.0f) * wob.z
            + fmaxf(d * a[7] + b2b.w, 0.0f) * wob.w;

    s += __shfl_xor_sync(0xffffffffu, s, 1);
    s += __shfl_xor_sync(0xffffffffu, s, 2);
    s += __shfl_xor_sync(0xffffffffu, s, 4);
    if (c == 0) out[i] = fmaxf(s + __ldg(bout), 0.0f);
}

// ---------------- launch ----------------------------------------------------
extern "C" void kernel_launch(void* const* d_in, const int* in_sizes, int n_in,
                              void* d_out, int out_size) {
    const float* x    = (const float*)d_in[0];
    const int*   ei   = (const int*)  d_in[1];
    const float* W1   = (const float*)d_in[2];
    const float* b1   = (const float*)d_in[3];
    const float* W2   = (const float*)d_in[4];
    const float* b2   = (const float*)d_in[5];
    const float* Wout = (const float*)d_in[6];
    const float* bout = (const float*)d_in[7];
    float* out = (float*)d_out;

    const int NB_N = (N_NODES + 255) / 256;
    const int NB_E = (N_EDGES + 255) / 256;
    const int NB_G1 = (N_NODES + 127) / 128;   // 1563 blocks, 128 rows each
    const int NB_G2 = (N_NODES + 127) / 128;
    const int NB_A = (N_NODES + 31) / 32;      // 6250

    k_deg_zero <<<NB_N, 256>>>();
    k_deg_count<<<NB_E, 256>>>(ei);
    k_dinv     <<<NB_N, 256>>>();
    k_gemm1    <<<NB_G1, 256>>>(x, W1);        // 4th launch -> ncu window
    k_scan1    <<<SCAN_NB, SCAN_B>>>();
    k_scan2    <<<1, 256>>>();
    k_scan3    <<<SCAN_NB, SCAN_B>>>();
    k_scatter  <<<NB_E, 256>>>(ei);
    k_agg1     <<<NB_A, 288>>>();
    k_gemm2    <<<NB_G2, 256>>>(W2, b1);
    k_agg2out  <<<NB_A, 256>>>(b2, Wout, bout, out);
}

// round 10
// speedup vs baseline: 1.7960x; 1.1777x over previous
#include <cuda_runtime.h>
#include <cuda_fp16.h>

#define N_NODES 200000
#define N_EDGES 6400000
#define D_IN    100
#define D_H1    65
#define H1H     72      // fp16 row pad: 9 x uint4 (8 halves each) = 144B
#define D_H2    64      // fp16 row: 8 x uint4 = 128B

#define SCAN_B  1024
#define SCAN_NB ((N_NODES + SCAN_B - 1) / SCAN_B)   // 196

// ---------------- scratch (device globals; no allocation allowed) -----------
__device__ uint4  g_h1h [(N_NODES * H1H) / 8];   // 28.8 MB  fp16 h1*dinv
__device__ uint4  g_a1h [(N_NODES * H1H) / 8];   // 28.8 MB  fp16 relu(agg1+b1)
__device__ uint4  g_h2h [(N_NODES * D_H2) / 8];  // 25.6 MB  fp16 h2*dinv
__device__ float  g_dinv[N_NODES];
__device__ int    g_deg [N_NODES];
__device__ int    g_rowptr[N_NODES + 1];
__device__ int    g_cursor[N_NODES];
__device__ int    g_esrc[N_EDGES];               // CSR: src ids grouped by dst
__device__ int    g_bsum[SCAN_NB];               // per-block scan totals

// ---------------- degree / dinv ---------------------------------------------
__global__ void k_deg_zero() {
    int i = blockIdx.x * blockDim.x + threadIdx.x;
    if (i < N_NODES) g_deg[i] = 0;
}

__global__ void k_deg_count(const int* __restrict__ ei) {
    int e = blockIdx.x * blockDim.x + threadIdx.x;
    if (e < N_EDGES) atomicAdd(&g_deg[ei[N_EDGES + e]], 1);   // dst = ei[1]
}

__global__ void k_dinv() {
    int i = blockIdx.x * blockDim.x + threadIdx.x;
    if (i < N_NODES) g_dinv[i] = rsqrtf((float)(g_deg[i] + 1));  // +1 self loop
}

// ---------------- GEMM1 (tensor core): hs1 = (x @ W1) * dinv -> fp16 --------
#define XS_STRIDE 57    // half2 words per row (56 data + 1 pad, odd stride)
__global__ __launch_bounds__(256) void k_gemm1(const float* __restrict__ x,
                                               const float* __restrict__ W1) {
    __shared__ __half2 Xs[128 * XS_STRIDE];  // 29.2 KB
    __shared__ __half2 Wsm[56 * 72];         // 16.1 KB  (k-pair, n)
    int t = threadIdx.x;
    int rbase = blockIdx.x * 128;

    for (int idx = t; idx < 56 * 72; idx += 256) {
        int kp = idx / 72, n = idx % 72;
        int k0 = 2 * kp;
        float lo = (k0 < D_IN && n < D_H1) ? W1[k0 * D_H1 + n] : 0.0f;
        float hi = (k0 + 1 < D_IN && n < D_H1) ? W1[(k0 + 1) * D_H1 + n] : 0.0f;
        Wsm[idx] = __floats2half2_rn(lo, hi);
    }

    for (int idx = t; idx < 128 * 56; idx += 256) {
        int rr = idx / 56, kp = idx % 56;
        int row = rbase + rr;
        __half2 v = __floats2half2_rn(0.0f, 0.0f);
        if (row < N_NODES && kp < 50) {
            float2 f2 = *(const float2*)(x + (size_t)row * D_IN + 2 * kp);
            v = __floats2half2_rn(f2.x, f2.y);
        }
        Xs[rr * XS_STRIDE + kp] = v;
    }
    __syncthreads();

    int w    = t >> 5;
    int lane = t & 31;
    int g    = lane >> 2;
    int tig  = lane & 3;
    int m0   = w * 16;

    float acc[9][4];
#pragma unroll
    for (int nt = 0; nt < 9; nt++)
#pragma unroll
        for (int j = 0; j < 4; j++) acc[nt][j] = 0.0f;

    const unsigned* XsU = (const unsigned*)Xs;
    const unsigned* WsU = (const unsigned*)Wsm;

#pragma unroll
    for (int ks = 0; ks < 7; ks++) {
        int kb = ks * 8;
        unsigned a0 = XsU[(m0 + g)     * XS_STRIDE + kb + tig];
        unsigned a1 = XsU[(m0 + g + 8) * XS_STRIDE + kb + tig];
        unsigned a2 = XsU[(m0 + g)     * XS_STRIDE + kb + 4 + tig];
        unsigned a3 = XsU[(m0 + g + 8) * XS_STRIDE + kb + 4 + tig];
#pragma unroll
        for (int nt = 0; nt < 9; nt++) {
            unsigned b0 = WsU[(kb + tig)     * 72 + nt * 8 + g];
            unsigned b1 = WsU[(kb + 4 + tig) * 72 + nt * 8 + g];
            asm volatile(
                "mma.sync.aligned.m16n8k16.row.col.f32.f16.f16.f32 "
                "{%0,%1,%2,%3}, {%4,%5,%6,%7}, {%8,%9}, {%0,%1,%2,%3};"
                : "+f"(acc[nt][0]), "+f"(acc[nt][1]),
                  "+f"(acc[nt][2]), "+f"(acc[nt][3])
                : "r"(a0), "r"(a1), "r"(a2), "r"(a3), "r"(b0), "r"(b1));
        }
    }

    __half2* h2out = (__half2*)g_h1h;          // row stride 36 half2
    int row0 = rbase + m0 + g;
    int row1 = row0 + 8;
    float d0 = (row0 < N_NODES) ? g_dinv[row0] : 0.0f;
    float d1 = (row1 < N_NODES) ? g_dinv[row1] : 0.0f;
#pragma unroll
    for (int nt = 0; nt < 9; nt++) {
        int cw = nt * 4 + tig;
        if (row0 < N_NODES)
            h2out[(unsigned)row0 * 36 + cw] =
                __floats2half2_rn(acc[nt][0] * d0, acc[nt][1] * d0);
        if (row1 < N_NODES)
            h2out[(unsigned)row1 * 36 + cw] =
                __floats2half2_rn(acc[nt][2] * d1, acc[nt][3] * d1);
    }
}

// ---------------- scan pass 1: per-block exclusive scan ----------------------
__global__ __launch_bounds__(SCAN_B) void k_scan1() {
    __shared__ int wsum[32];
    int t = threadIdx.x, lane = t & 31, wid = t >> 5;
    int idx = blockIdx.x * SCAN_B + t;
    int v = (idx < N_NODES) ? g_deg[idx] : 0;
    int x = v;
#pragma unroll
    for (int off = 1; off < 32; off <<= 1) {
        int n = __shfl_up_sync(0xffffffffu, x, off);
        if (lane >= off) x += n;
    }
    if (lane == 31) wsum[wid] = x;
    __syncthreads();
    if (wid == 0) {
        int w = wsum[lane];
#pragma unroll
        for (int off = 1; off < 32; off <<= 1) {
            int n = __shfl_up_sync(0xffffffffu, w, off);
            if (lane >= off) w += n;
        }
        wsum[lane] = w;
    }
    __syncthreads();
    int warpoff = (wid > 0) ? wsum[wid - 1] : 0;
    int excl = x - v + warpoff;
    if (idx < N_NODES) g_rowptr[idx] = excl;
    if (t == SCAN_B - 1) g_bsum[blockIdx.x] = warpoff + x;
}

// ---------------- scan pass 2 ------------------------------------------------
__global__ __launch_bounds__(256) void k_scan2() {
    __shared__ int wsum[8];
    int t = threadIdx.x, lane = t & 31, wid = t >> 5;
    int v = (t < SCAN_NB) ? g_bsum[t] : 0;
    int x = v;
#pragma unroll
    for (int off = 1; off < 32; off <<= 1) {
        int n = __shfl_up_sync(0xffffffffu, x, off);
        if (lane >= off) x += n;
    }
    if (lane == 31) wsum[wid] = x;
    __syncthreads();
    if (wid == 0 && lane < 8) {
        int w = wsum[lane];
#pragma unroll
        for (int off = 1; off < 8; off <<= 1) {
            int n = __shfl_up_sync(0xffu, w, off);
            if (lane >= off) w += n;
        }
        wsum[lane] = w;
    }
    __syncthreads();
    int warpoff = (wid > 0) ? wsum[wid - 1] : 0;
    int excl = x - v + warpoff;
    if (t < SCAN_NB) g_bsum[t] = excl;
    if (t == SCAN_NB - 1) g_rowptr[N_NODES] = excl + v;
}

// ---------------- scan pass 3 ------------------------------------------------
__global__ __launch_bounds__(SCAN_B) void k_scan3() {
    int idx = blockIdx.x * SCAN_B + threadIdx.x;
    if (idx < N_NODES) {
        int r = g_rowptr[idx] + g_bsum[blockIdx.x];
        g_rowptr[idx] = r;
        g_cursor[idx] = r;
    }
}

// ---------------- scatter edges into CSR ------------------------------------
__global__ void k_scatter(const int* __restrict__ ei) {
    int e = blockIdx.x * blockDim.x + threadIdx.x;
    if (e < N_EDGES) {
        int s = ei[e];
        int d = ei[N_EDGES + e];
        int pos = atomicAdd(&g_cursor[d], 1);
        g_esrc[pos] = s;
    }
}

// ---------------- fp16 chunk accumulate --------------------------------------
__device__ __forceinline__ void acc_chunk(float* a, uint4 q) {
    const __half2* hp = (const __half2*)&q;
#pragma unroll
    for (int j = 0; j < 4; j++) {
        float2 f = __half22float2(hp[j]);
        a[2 * j]     += f.x;
        a[2 * j + 1] += f.y;
    }
}

// ------ agg1: a1h[i] = fp16( relu( dinv[i]*(hs1[i] + sum hs1[src]) + b1 ) ) --
// 9 chunk-threads per node, 32 nodes per 288-thread block.
__global__ __launch_bounds__(288) void k_agg1(const float* __restrict__ b1) {
    int t  = threadIdx.x;
    int ln = t / 9;
    int c  = t - ln * 9;
    int i  = blockIdx.x * 32 + ln;
    if (i >= N_NODES) return;

    const uint4* hs = (const uint4*)g_h1h;      // N x 9 chunks
    int beg = __ldg(&g_rowptr[i]);
    int end = __ldg(&g_rowptr[i + 1]);

    float a[8] = {0, 0, 0, 0, 0, 0, 0, 0};
    acc_chunk(a, __ldg(&hs[(unsigned)i * 9 + c]));      // self loop

    int k = beg;
    for (; k + 3 < end; k += 4) {
        int s0 = __ldg(&g_esrc[k]);
        int s1 = __ldg(&g_esrc[k + 1]);
        int s2 = __ldg(&g_esrc[k + 2]);
        int s3 = __ldg(&g_esrc[k + 3]);
        uint4 q0 = __ldg(&hs[(unsigned)s0 * 9 + c]);
        uint4 q1 = __ldg(&hs[(unsigned)s1 * 9 + c]);
        uint4 q2 = __ldg(&hs[(unsigned)s2 * 9 + c]);
        uint4 q3 = __ldg(&hs[(unsigned)s3 * 9 + c]);
        acc_chunk(a, q0); acc_chunk(a, q1); acc_chunk(a, q2); acc_chunk(a, q3);
    }
    for (; k < end; k++) {
        int s = __ldg(&g_esrc[k]);
        acc_chunk(a, __ldg(&hs[(unsigned)s * 9 + c]));
    }

    float d = __ldg(&g_dinv[i]);
    uint4 u;
    __half2* hp = (__half2*)&u;
#pragma unroll
    for (int j = 0; j < 4; j++) {
        int col = 8 * c + 2 * j;
        float bv0 = (col     < D_H1) ? __ldg(b1 + col)     : 0.0f;
        float bv1 = (col + 1 < D_H1) ? __ldg(b1 + col + 1) : 0.0f;
        float v0 = fmaxf(d * a[2 * j]     + bv0, 0.0f);
        float v1 = fmaxf(d * a[2 * j + 1] + bv1, 0.0f);
        hp[j] = __floats2half2_rn(v0, v1);
    }
    g_a1h[(unsigned)i * 9 + c] = u;
}

// ---------------- GEMM2 (tensor core): hs2 = (a1h @ W2) * dinv -> fp16 ------
// K: 72 -> 80 (5 k-steps). N = 64 (8 n-tiles). Same fragment scheme as gemm1.
#define XS2_STRIDE 41   // half2 words per row (40 data + 1 pad, odd stride)
__global__ __launch_bounds__(256) void k_gemm2(const float* __restrict__ W2) {
    __shared__ __half2 Xs[128 * XS2_STRIDE]; // 21.0 KB
    __shared__ __half2 Wsm[40 * 72];         // 11.5 KB (stride 72: conflict-free)
    int t = threadIdx.x;
    int rbase = blockIdx.x * 128;

    for (int idx = t; idx < 40 * 72; idx += 256) {
        int kp = idx / 72, n = idx % 72;
        int k0 = 2 * kp;
        float lo = (k0 < D_H1 && n < D_H2) ? W2[k0 * D_H2 + n] : 0.0f;
        float hi = (k0 + 1 < D_H1 && n < D_H2) ? W2[(k0 + 1) * D_H2 + n] : 0.0f;
        Wsm[idx] = __floats2half2_rn(lo, hi);
    }

    const __half2* a1 = (const __half2*)g_a1h;   // row stride 36 half2
    for (int idx = t; idx < 128 * 40; idx += 256) {
        int rr = idx / 40, kp = idx % 40;
        int row = rbase + rr;
        __half2 v = __floats2half2_rn(0.0f, 0.0f);
        if (row < N_NODES && kp < 36) v = a1[(unsigned)row * 36 + kp];
        Xs[rr * XS2_STRIDE + kp] = v;
    }
    __syncthreads();

    int w    = t >> 5;
    int lane = t & 31;
    int g    = lane >> 2;
    int tig  = lane & 3;
    int m0   = w * 16;

    float acc[8][4];
#pragma unroll
    for (int nt = 0; nt < 8; nt++)
#pragma unroll
        for (int j = 0; j < 4; j++) acc[nt][j] = 0.0f;

    const unsigned* XsU = (const unsigned*)Xs;
    const unsigned* WsU = (const unsigned*)Wsm;

#pragma unroll
    for (int ks = 0; ks < 5; ks++) {
        int kb = ks * 8;
        unsigned a0 = XsU[(m0 + g)     * XS2_STRIDE + kb + tig];
        unsigned a1r= XsU[(m0 + g + 8) * XS2_STRIDE + kb + tig];
        unsigned a2 = XsU[(m0 + g)     * XS2_STRIDE + kb + 4 + tig];
        unsigned a3 = XsU[(m0 + g + 8) * XS2_STRIDE + kb + 4 + tig];
#pragma unroll
        for (int nt = 0; nt < 8; nt++) {
            unsigned b0 = WsU[(kb + tig)     * 72 + nt * 8 + g];
            unsigned b1 = WsU[(kb + 4 + tig) * 72 + nt * 8 + g];
            asm volatile(
                "mma.sync.aligned.m16n8k16.row.col.f32.f16.f16.f32 "
                "{%0,%1,%2,%3}, {%4,%5,%6,%7}, {%8,%9}, {%0,%1,%2,%3};"
                : "+f"(acc[nt][0]), "+f"(acc[nt][1]),
                  "+f"(acc[nt][2]), "+f"(acc[nt][3])
                : "r"(a0), "r"(a1r), "r"(a2), "r"(a3), "r"(b0), "r"(b1));
        }
    }

    __half2* h2out = (__half2*)g_h2h;          // row stride 32 half2
    int row0 = rbase + m0 + g;
    int row1 = row0 + 8;
    float d0 = (row0 < N_NODES) ? g_dinv[row0] : 0.0f;
    float d1 = (row1 < N_NODES) ? g_dinv[row1] : 0.0f;
#pragma unroll
    for (int nt = 0; nt < 8; nt++) {
        int cw = nt * 4 + tig;
        if (row0 < N_NODES)
            h2out[(unsigned)row0 * 32 + cw] =
                __floats2half2_rn(acc[nt][0] * d0, acc[nt][1] * d0);
        if (row1 < N_NODES)
            h2out[(unsigned)row1 * 32 + cw] =
                __floats2half2_rn(acc[nt][2] * d1, acc[nt][3] * d1);
    }
}

// ------- agg2 + output fused: out[i]=relu(sum_c relu(agg2_c+b2)*Wout + bout) -
__global__ __launch_bounds__(256) void k_agg2out(const float* __restrict__ b2,
                                                 const float* __restrict__ Wout,
                                                 const float* __restrict__ bout,
                                                 float* __restrict__ out) {
    int t  = threadIdx.x;
    int ln = t >> 3;
    int c  = t & 7;
    int i  = blockIdx.x * 32 + ln;
    if (i >= N_NODES) return;

    const uint4* hs = (const uint4*)g_h2h;      // N x 8 chunks
    int beg = __ldg(&g_rowptr[i]);
    int end = __ldg(&g_rowptr[i + 1]);

    float a[8] = {0, 0, 0, 0, 0, 0, 0, 0};
    acc_chunk(a, __ldg(&hs[(unsigned)i * 8 + c]));      // self loop

    int k = beg;
    for (; k + 3 < end; k += 4) {
        int s0 = __ldg(&g_esrc[k]);
        int s1 = __ldg(&g_esrc[k + 1]);
        int s2 = __ldg(&g_esrc[k + 2]);
        int s3 = __ldg(&g_esrc[k + 3]);
        uint4 q0 = __ldg(&hs[(unsigned)s0 * 8 + c]);
        uint4 q1 = __ldg(&hs[(unsigned)s1 * 8 + c]);
        uint4 q2 = __ldg(&hs[(unsigned)s2 * 8 + c]);
        uint4 q3 = __ldg(&hs[(unsigned)s3 * 8 + c]);
        acc_chunk(a, q0); acc_chunk(a, q1); acc_chunk(a, q2); acc_chunk(a, q3);
    }
    for (; k < end; k++) {
        int s = __ldg(&g_esrc[k]);
        acc_chunk(a, __ldg(&hs[(unsigned)s * 8 + c]));
    }

    float d = __ldg(&g_dinv[i]);
    float4 b2a = __ldg((const float4*)b2 + c * 2);
    float4 b2b = __ldg((const float4*)b2 + c * 2 + 1);
    float4 woa = __ldg((const float4*)Wout + c * 2);
    float4 wob = __ldg((const float4*)Wout + c * 2 + 1);

    float s = fmaxf(d * a[0] + b2a.x, 0.0f) * woa.x
            + fmaxf(d * a[1] + b2a.y, 0.0f) * woa.y
            + fmaxf(d * a[2] + b2a.z, 0.0f) * woa.z
            + fmaxf(d * a[3] + b2a.w, 0.0f) * woa.w
            + fmaxf(d * a[4] + b2b.x, 0.0f) * wob.x
            + fmaxf(d * a[5] + b2b.y, 0.0f) * wob.y
            + fmaxf(d * a[6] + b2b.z, 0.0f) * wob.z
            + fmaxf(d * a[7] + b2b.w, 0.0f) * wob.w;

    s += __shfl_xor_sync(0xffffffffu, s, 1);
    s += __shfl_xor_sync(0xffffffffu, s, 2);
    s += __shfl_xor_sync(0xffffffffu, s, 4);
    if (c == 0) out[i] = fmaxf(s + __ldg(bout), 0.0f);
}

// ---------------- launch ----------------------------------------------------
extern "C" void kernel_launch(void* const* d_in, const int* in_sizes, int n_in,
                              void* d_out, int out_size) {
    const float* x    = (const float*)d_in[0];
    const int*   ei   = (const int*)  d_in[1];
    const float* W1   = (const float*)d_in[2];
    const float* b1   = (const float*)d_in[3];
    const float* W2   = (const float*)d_in[4];
    const float* b2   = (const float*)d_in[5];
    const float* Wout = (const float*)d_in[6];
    const float* bout = (const float*)d_in[7];
    float* out = (float*)d_out;

    const int NB_N = (N_NODES + 255) / 256;
    const int NB_E = (N_EDGES + 255) / 256;
    const int NB_G = (N_NODES + 127) / 128;   // 1563 blocks, 128 rows each
    const int NB_A = (N_NODES + 31) / 32;     // 6250

    k_deg_zero <<<NB_N, 256>>>();
    k_deg_count<<<NB_E, 256>>>(ei);
    k_dinv     <<<NB_N, 256>>>();
    k_gemm1    <<<NB_G, 256>>>(x, W1);        // 4th launch -> ncu window
    k_scan1    <<<SCAN_NB, SCAN_B>>>();
    k_scan2    <<<1, 256>>>();
    k_scan3    <<<SCAN_NB, SCAN_B>>>();
    k_scatter  <<<NB_E, 256>>>(ei);
    k_agg1     <<<NB_A, 288>>>(b1);
    k_gemm2    <<<NB_G, 256>>>(W2);
    k_agg2out  <<<NB_A, 256>>>(b2, Wout, bout, out);
}

// round 11
// speedup vs baseline: 1.8292x; 1.0185x over previous
#include <cuda_runtime.h>
#include <cuda_fp16.h>

#define N_NODES 200000
#define N_EDGES 6400000
#define D_IN    100
#define D_H1    65
#define H1H     72      // fp16 row pad: 9 x uint4 (8 halves each) = 144B
#define D_H2    64      // fp16 row: 8 x uint4 = 128B

#define SCAN_B  1024
#define SCAN_NB ((N_NODES + SCAN_B - 1) / SCAN_B)   // 196

// ---------------- scratch (device globals; no allocation allowed) -----------
__device__ uint4  g_h1h [(N_NODES * H1H) / 8];   // 28.8 MB  fp16 h1*dinv
__device__ uint4  g_a1h [(N_NODES * H1H) / 8];   // 28.8 MB  fp16 relu(agg1+b1)
__device__ uint4  g_h2h [(N_NODES * D_H2) / 8];  // 25.6 MB  fp16 h2*dinv
__device__ float  g_dinv[N_NODES];
__device__ int    g_deg [N_NODES];
__device__ int    g_rowptr[N_NODES + 1];
__device__ int    g_cursor[N_NODES];
__device__ int    g_esrc[N_EDGES];               // CSR: src ids grouped by dst
__device__ int    g_bsum[SCAN_NB];               // per-block scan totals

// ---------------- degree -----------------------------------------------------
__global__ void k_deg_zero() {
    int i = blockIdx.x * blockDim.x + threadIdx.x;
    if (i < N_NODES) g_deg[i] = 0;
}

__global__ void k_deg_count(const int* __restrict__ ei) {
    int e = blockIdx.x * blockDim.x + threadIdx.x;
    if (e < N_EDGES) atomicAdd(&g_deg[ei[N_EDGES + e]], 1);   // dst = ei[1]
}

// ---------------- scan pass 1 (+ fused dinv) ---------------------------------
__global__ __launch_bounds__(SCAN_B) void k_scan1() {
    __shared__ int wsum[32];
    int t = threadIdx.x, lane = t & 31, wid = t >> 5;
    int idx = blockIdx.x * SCAN_B + t;
    int v = (idx < N_NODES) ? g_deg[idx] : 0;
    int x = v;
#pragma unroll
    for (int off = 1; off < 32; off <<= 1) {
        int n = __shfl_up_sync(0xffffffffu, x, off);
        if (lane >= off) x += n;
    }
    if (lane == 31) wsum[wid] = x;
    __syncthreads();
    if (wid == 0) {
        int w = wsum[lane];
#pragma unroll
        for (int off = 1; off < 32; off <<= 1) {
            int n = __shfl_up_sync(0xffffffffu, w, off);
            if (lane >= off) w += n;
        }
        wsum[lane] = w;
    }
    __syncthreads();
    int warpoff = (wid > 0) ? wsum[wid - 1] : 0;
    int excl = x - v + warpoff;
    if (idx < N_NODES) {
        g_rowptr[idx] = excl;
        g_dinv[idx]   = rsqrtf((float)(v + 1));   // +1 self loop
    }
    if (t == SCAN_B - 1) g_bsum[blockIdx.x] = warpoff + x;
}

// ---------------- GEMM1 (tensor core): hs1 = (x @ W1) * dinv -> fp16 --------
#define XS_STRIDE 57    // half2 words per row (56 data + 1 pad, odd stride)
__global__ __launch_bounds__(256) void k_gemm1(const float* __restrict__ x,
                                               const float* __restrict__ W1) {
    __shared__ __half2 Xs[128 * XS_STRIDE];  // 29.2 KB
    __shared__ __half2 Wsm[56 * 72];         // 16.1 KB  (k-pair, n)
    int t = threadIdx.x;
    int rbase = blockIdx.x * 128;

    // W staging: idx = t + 256*i ; (kp, n) updated incrementally (256 = 3*72+40)
    {
        int kp = t / 72, n = t - kp * 72;
        for (int idx = t; idx < 56 * 72; idx += 256) {
            int k0 = 2 * kp;
            float lo = (k0 < D_IN && n < D_H1) ? W1[k0 * D_H1 + n] : 0.0f;
            float hi = (k0 + 1 < D_IN && n < D_H1) ? W1[(k0 + 1) * D_H1 + n] : 0.0f;
            Wsm[kp * 72 + n] = __floats2half2_rn(lo, hi);
            kp += 3; n += 40;
            if (n >= 72) { n -= 72; kp += 1; }
        }
    }

    // X staging: (rr, kp) incremental (256 = 4*56+32)
    {
        int rr = t / 56, kp = t - rr * 56;
        for (int idx = t; idx < 128 * 56; idx += 256) {
            int row = rbase + rr;
            __half2 v = __floats2half2_rn(0.0f, 0.0f);
            if (row < N_NODES && kp < 50) {
                float2 f2 = *(const float2*)(x + (size_t)row * D_IN + 2 * kp);
                v = __floats2half2_rn(f2.x, f2.y);
            }
            Xs[rr * XS_STRIDE + kp] = v;
            rr += 4; kp += 32;
            if (kp >= 56) { kp -= 56; rr += 1; }
        }
    }
    __syncthreads();

    int w    = t >> 5;
    int lane = t & 31;
    int g    = lane >> 2;
    int tig  = lane & 3;
    int m0   = w * 16;

    float acc[9][4];
#pragma unroll
    for (int nt = 0; nt < 9; nt++)
#pragma unroll
        for (int j = 0; j < 4; j++) acc[nt][j] = 0.0f;

    const unsigned* XsU = (const unsigned*)Xs;
    const unsigned* WsU = (const unsigned*)Wsm;

#pragma unroll
    for (int ks = 0; ks < 7; ks++) {
        int kb = ks * 8;
        unsigned a0 = XsU[(m0 + g)     * XS_STRIDE + kb + tig];
        unsigned a1 = XsU[(m0 + g + 8) * XS_STRIDE + kb + tig];
        unsigned a2 = XsU[(m0 + g)     * XS_STRIDE + kb + 4 + tig];
        unsigned a3 = XsU[(m0 + g + 8) * XS_STRIDE + kb + 4 + tig];
#pragma unroll
        for (int nt = 0; nt < 9; nt++) {
            unsigned b0 = WsU[(kb + tig)     * 72 + nt * 8 + g];
            unsigned b1 = WsU[(kb + 4 + tig) * 72 + nt * 8 + g];
            asm volatile(
                "mma.sync.aligned.m16n8k16.row.col.f32.f16.f16.f32 "
                "{%0,%1,%2,%3}, {%4,%5,%6,%7}, {%8,%9}, {%0,%1,%2,%3};"
                : "+f"(acc[nt][0]), "+f"(acc[nt][1]),
                  "+f"(acc[nt][2]), "+f"(acc[nt][3])
                : "r"(a0), "r"(a1), "r"(a2), "r"(a3), "r"(b0), "r"(b1));
        }
    }

    __half2* h2out = (__half2*)g_h1h;          // row stride 36 half2
    int row0 = rbase + m0 + g;
    int row1 = row0 + 8;
    float d0 = (row0 < N_NODES) ? g_dinv[row0] : 0.0f;
    float d1 = (row1 < N_NODES) ? g_dinv[row1] : 0.0f;
#pragma unroll
    for (int nt = 0; nt < 9; nt++) {
        int cw = nt * 4 + tig;
        if (row0 < N_NODES)
            h2out[(unsigned)row0 * 36 + cw] =
                __floats2half2_rn(acc[nt][0] * d0, acc[nt][1] * d0);
        if (row1 < N_NODES)
            h2out[(unsigned)row1 * 36 + cw] =
                __floats2half2_rn(acc[nt][2] * d1, acc[nt][3] * d1);
    }
}

// ---------------- scan pass 2 ------------------------------------------------
__global__ __launch_bounds__(256) void k_scan2() {
    __shared__ int wsum[8];
    int t = threadIdx.x, lane = t & 31, wid = t >> 5;
    int v = (t < SCAN_NB) ? g_bsum[t] : 0;
    int x = v;
#pragma unroll
    for (int off = 1; off < 32; off <<= 1) {
        int n = __shfl_up_sync(0xffffffffu, x, off);
        if (lane >= off) x += n;
    }
    if (lane == 31) wsum[wid] = x;
    __syncthreads();
    if (wid == 0 && lane < 8) {
        int w = wsum[lane];
#pragma unroll
        for (int off = 1; off < 8; off <<= 1) {
            int n = __shfl_up_sync(0xffu, w, off);
            if (lane >= off) w += n;
        }
        wsum[lane] = w;
    }
    __syncthreads();
    int warpoff = (wid > 0) ? wsum[wid - 1] : 0;
    int excl = x - v + warpoff;
    if (t < SCAN_NB) g_bsum[t] = excl;
    if (t == SCAN_NB - 1) g_rowptr[N_NODES] = excl + v;
}

// ---------------- scan pass 3 ------------------------------------------------
__global__ __launch_bounds__(SCAN_B) void k_scan3() {
    int idx = blockIdx.x * SCAN_B + threadIdx.x;
    if (idx < N_NODES) {
        int r = g_rowptr[idx] + g_bsum[blockIdx.x];
        g_rowptr[idx] = r;
        g_cursor[idx] = r;
    }
}

// ---------------- scatter edges into CSR ------------------------------------
__global__ void k_scatter(const int* __restrict__ ei) {
    int e = blockIdx.x * blockDim.x + threadIdx.x;
    if (e < N_EDGES) {
        int s = ei[e];
        int d = ei[N_EDGES + e];
        int pos = atomicAdd(&g_cursor[d], 1);
        g_esrc[pos] = s;
    }
}

// ---------------- fp16 chunk accumulate --------------------------------------
__device__ __forceinline__ void acc_chunk(float* a, uint4 q) {
    const __half2* hp = (const __half2*)&q;
#pragma unroll
    for (int j = 0; j < 4; j++) {
        float2 f = __half22float2(hp[j]);
        a[2 * j]     += f.x;
        a[2 * j + 1] += f.y;
    }
}

// ------ agg1: a1h[i] = fp16( relu( dinv[i]*(hs1[i] + sum hs1[src]) + b1 ) ) --
__global__ __launch_bounds__(288) void k_agg1(const float* __restrict__ b1) {
    int t  = threadIdx.x;
    int ln = t / 9;
    int c  = t - ln * 9;
    int i  = blockIdx.x * 32 + ln;
    if (i >= N_NODES) return;

    const uint4* hs = (const uint4*)g_h1h;      // N x 9 chunks
    int beg = __ldg(&g_rowptr[i]);
    int end = __ldg(&g_rowptr[i + 1]);

    float a[8] = {0, 0, 0, 0, 0, 0, 0, 0};
    acc_chunk(a, __ldg(&hs[(unsigned)i * 9 + c]));      // self loop

    int k = beg;
    for (; k + 3 < end; k += 4) {
        int s0 = __ldg(&g_esrc[k]);
        int s1 = __ldg(&g_esrc[k + 1]);
        int s2 = __ldg(&g_esrc[k + 2]);
        int s3 = __ldg(&g_esrc[k + 3]);
        uint4 q0 = __ldg(&hs[(unsigned)s0 * 9 + c]);
        uint4 q1 = __ldg(&hs[(unsigned)s1 * 9 + c]);
        uint4 q2 = __ldg(&hs[(unsigned)s2 * 9 + c]);
        uint4 q3 = __ldg(&hs[(unsigned)s3 * 9 + c]);
        acc_chunk(a, q0); acc_chunk(a, q1); acc_chunk(a, q2); acc_chunk(a, q3);
    }
    for (; k < end; k++) {
        int s = __ldg(&g_esrc[k]);
        acc_chunk(a, __ldg(&hs[(unsigned)s * 9 + c]));
    }

    float d = __ldg(&g_dinv[i]);
    uint4 u;
    __half2* hp = (__half2*)&u;
#pragma unroll
    for (int j = 0; j < 4; j++) {
        int col = 8 * c + 2 * j;
        float bv0 = (col     < D_H1) ? __ldg(b1 + col)     : 0.0f;
        float bv1 = (col + 1 < D_H1) ? __ldg(b1 + col + 1) : 0.0f;
        float v0 = fmaxf(d * a[2 * j]     + bv0, 0.0f);
        float v1 = fmaxf(d * a[2 * j + 1] + bv1, 0.0f);
        hp[j] = __floats2half2_rn(v0, v1);
    }
    g_a1h[(unsigned)i * 9 + c] = u;
}

// ---------------- GEMM2 (tensor core): hs2 = (a1h @ W2) * dinv -> fp16 ------
#define XS2_STRIDE 41   // half2 words per row (40 data + 1 pad, odd stride)
__global__ __launch_bounds__(256) void k_gemm2(const float* __restrict__ W2) {
    __shared__ __half2 Xs[128 * XS2_STRIDE]; // 21.0 KB
    __shared__ __half2 Wsm[40 * 72];         // 11.5 KB
    int t = threadIdx.x;
    int rbase = blockIdx.x * 128;

    // W staging incremental (256 = 3*72+40)
    {
        int kp = t / 72, n = t - kp * 72;
        for (int idx = t; idx < 40 * 72; idx += 256) {
            int k0 = 2 * kp;
            float lo = (k0 < D_H1 && n < D_H2) ? W2[k0 * D_H2 + n] : 0.0f;
            float hi = (k0 + 1 < D_H1 && n < D_H2) ? W2[(k0 + 1) * D_H2 + n] : 0.0f;
            Wsm[kp * 72 + n] = __floats2half2_rn(lo, hi);
            kp += 3; n += 40;
            if (n >= 72) { n -= 72; kp += 1; }
        }
    }

    // X staging incremental (256 = 6*40+16)
    {
        const __half2* a1 = (const __half2*)g_a1h;   // row stride 36 half2
        int rr = t / 40, kp = t - rr * 40;
        for (int idx = t; idx < 128 * 40; idx += 256) {
            int row = rbase + rr;
            __half2 v = __floats2half2_rn(0.0f, 0.0f);
            if (row < N_NODES && kp < 36) v = a1[(unsigned)row * 36 + kp];
            Xs[rr * XS2_STRIDE + kp] = v;
            rr += 6; kp += 16;
            if (kp >= 40) { kp -= 40; rr += 1; }
        }
    }
    __syncthreads();

    int w    = t >> 5;
    int lane = t & 31;
    int g    = lane >> 2;
    int tig  = lane & 3;
    int m0   = w * 16;

    float acc[8][4];
#pragma unroll
    for (int nt = 0; nt < 8; nt++)
#pragma unroll
        for (int j = 0; j < 4; j++) acc[nt][j] = 0.0f;

    const unsigned* XsU = (const unsigned*)Xs;
    const unsigned* WsU = (const unsigned*)Wsm;

#pragma unroll
    for (int ks = 0; ks < 5; ks++) {
        int kb = ks * 8;
        unsigned a0 = XsU[(m0 + g)     * XS2_STRIDE + kb + tig];
        unsigned a1r= XsU[(m0 + g + 8) * XS2_STRIDE + kb + tig];
        unsigned a2 = XsU[(m0 + g)     * XS2_STRIDE + kb + 4 + tig];
        unsigned a3 = XsU[(m0 + g + 8) * XS2_STRIDE + kb + 4 + tig];
#pragma unroll
        for (int nt = 0; nt < 8; nt++) {
            unsigned b0 = WsU[(kb + tig)     * 72 + nt * 8 + g];
            unsigned b1 = WsU[(kb + 4 + tig) * 72 + nt * 8 + g];
            asm volatile(
                "mma.sync.aligned.m16n8k16.row.col.f32.f16.f16.f32 "
                "{%0,%1,%2,%3}, {%4,%5,%6,%7}, {%8,%9}, {%0,%1,%2,%3};"
                : "+f"(acc[nt][0]), "+f"(acc[nt][1]),
                  "+f"(acc[nt][2]), "+f"(acc[nt][3])
                : "r"(a0), "r"(a1r), "r"(a2), "r"(a3), "r"(b0), "r"(b1));
        }
    }

    __half2* h2out = (__half2*)g_h2h;          // row stride 32 half2
    int row0 = rbase + m0 + g;
    int row1 = row0 + 8;
    float d0 = (row0 < N_NODES) ? g_dinv[row0] : 0.0f;
    float d1 = (row1 < N_NODES) ? g_dinv[row1] : 0.0f;
#pragma unroll
    for (int nt = 0; nt < 8; nt++) {
        int cw = nt * 4 + tig;
        if (row0 < N_NODES)
            h2out[(unsigned)row0 * 32 + cw] =
                __floats2half2_rn(acc[nt][0] * d0, acc[nt][1] * d0);
        if (row1 < N_NODES)
            h2out[(unsigned)row1 * 32 + cw] =
                __floats2half2_rn(acc[nt][2] * d1, acc[nt][3] * d1);
    }
}

// ------- agg2 + output fused: out[i]=relu(sum_c relu(agg2_c+b2)*Wout + bout) -
__global__ __launch_bounds__(256) void k_agg2out(const float* __restrict__ b2,
                                                 const float* __restrict__ Wout,
                                                 const float* __restrict__ bout,
                                                 float* __restrict__ out) {
    int t  = threadIdx.x;
    int ln = t >> 3;
    int c  = t & 7;
    int i  = blockIdx.x * 32 + ln;
    if (i >= N_NODES) return;

    const uint4* hs = (const uint4*)g_h2h;      // N x 8 chunks
    int beg = __ldg(&g_rowptr[i]);
    int end = __ldg(&g_rowptr[i + 1]);

    float a[8] = {0, 0, 0, 0, 0, 0, 0, 0};
    acc_chunk(a, __ldg(&hs[(unsigned)i * 8 + c]));      // self loop

    int k = beg;
    for (; k + 3 < end; k += 4) {
        int s0 = __ldg(&g_esrc[k]);
        int s1 = __ldg(&g_esrc[k + 1]);
        int s2 = __ldg(&g_esrc[k + 2]);
        int s3 = __ldg(&g_esrc[k + 3]);
        uint4 q0 = __ldg(&hs[(unsigned)s0 * 8 + c]);
        uint4 q1 = __ldg(&hs[(unsigned)s1 * 8 + c]);
        uint4 q2 = __ldg(&hs[(unsigned)s2 * 8 + c]);
        uint4 q3 = __ldg(&hs[(unsigned)s3 * 8 + c]);
        acc_chunk(a, q0); acc_chunk(a, q1); acc_chunk(a, q2); acc_chunk(a, q3);
    }
    for (; k < end; k++) {
        int s = __ldg(&g_esrc[k]);
        acc_chunk(a, __ldg(&hs[(unsigned)s * 8 + c]));
    }

    float d = __ldg(&g_dinv[i]);
    float4 b2a = __ldg((const float4*)b2 + c * 2);
    float4 b2b = __ldg((const float4*)b2 + c * 2 + 1);
    float4 woa = __ldg((const float4*)Wout + c * 2);
    float4 wob = __ldg((const float4*)Wout + c * 2 + 1);

    float s = fmaxf(d * a[0] + b2a.x, 0.0f) * woa.x
            + fmaxf(d * a[1] + b2a.y, 0.0f) * woa.y
            + fmaxf(d * a[2] + b2a.z, 0.0f) * woa.z
            + fmaxf(d * a[3] + b2a.w, 0.0f) * woa.w
            + fmaxf(d * a[4] + b2b.x, 0.0f) * wob.x
            + fmaxf(d * a[5] + b2b.y, 0.0f) * wob.y
            + fmaxf(d * a[6] + b2b.z, 0.0f) * wob.z
            + fmaxf(d * a[7] + b2b.w, 0.0f) * wob.w;

    s += __shfl_xor_sync(0xffffffffu, s, 1);
    s += __shfl_xor_sync(0xffffffffu, s, 2);
    s += __shfl_xor_sync(0xffffffffu, s, 4);
    if (c == 0) out[i] = fmaxf(s + __ldg(bout), 0.0f);
}

// ---------------- launch ----------------------------------------------------
extern "C" void kernel_launch(void* const* d_in, const int* in_sizes, int n_in,
                              void* d_out, int out_size) {
    const float* x    = (const float*)d_in[0];
    const int*   ei   = (const int*)  d_in[1];
    const float* W1   = (const float*)d_in[2];
    const float* b1   = (const float*)d_in[3];
    const float* W2   = (const float*)d_in[4];
    const float* b2   = (const float*)d_in[5];
    const float* Wout = (const float*)d_in[6];
    const float* bout = (const float*)d_in[7];
    float* out = (float*)d_out;

    const int NB_N = (N_NODES + 255) / 256;
    const int NB_E = (N_EDGES + 255) / 256;
    const int NB_G = (N_NODES + 127) / 128;   // 1563 blocks, 128 rows each
    const int NB_A = (N_NODES + 31) / 32;     // 6250

    k_deg_zero <<<NB_N, 256>>>();
    k_deg_count<<<NB_E, 256>>>(ei);
    k_scan1    <<<SCAN_NB, SCAN_B>>>();       // also computes dinv
    k_gemm1    <<<NB_G, 256>>>(x, W1);        // 4th launch -> ncu window
    k_scan2    <<<1, 256>>>();
    k_scan3    <<<SCAN_NB, SCAN_B>>>();
    k_scatter  <<<NB_E, 256>>>(ei);
    k_agg1     <<<NB_A, 288>>>(b1);
    k_gemm2    <<<NB_G, 256>>>(W2);
    k_agg2out  <<<NB_A, 256>>>(b2, Wout, bout, out);
}

// round 12
// speedup vs baseline: 1.8352x; 1.0033x over previous
#include <cuda_runtime.h>
#include <cuda_fp16.h>

#define N_NODES 200000
#define N_EDGES 6400000
#define D_IN    100
#define D_H1    65
#define H1H     72      // fp16 row pad: 9 x uint4 (8 halves each) = 144B
#define D_H2    64      // fp16 row: 8 x uint4 = 128B

#define SCAN_B  1024
#define SCAN_NB ((N_NODES + SCAN_B - 1) / SCAN_B)   // 196

// ---------------- scratch (device globals; no allocation allowed) -----------
__device__ uint4  g_h1h [(N_NODES * H1H) / 8];   // 28.8 MB  fp16 h1*dinv
__device__ uint4  g_a1h [(N_NODES * H1H) / 8];   // 28.8 MB  fp16 relu(agg1+b1)
__device__ uint4  g_h2h [(N_NODES * D_H2) / 8];  // 25.6 MB  fp16 h2*dinv
__device__ float  g_dinv[N_NODES];
__device__ int    g_deg [N_NODES];
__device__ int    g_rowptr[N_NODES + 1];
__device__ int    g_cursor[N_NODES];
__device__ int    g_esrc[N_EDGES];               // CSR: src ids grouped by dst
__device__ int    g_bsum[SCAN_NB];               // per-block scan totals

// ---------------- degree -----------------------------------------------------
__global__ void k_deg_zero() {
    int i = blockIdx.x * blockDim.x + threadIdx.x;
    if (i < N_NODES) g_deg[i] = 0;
}

__global__ void k_deg_count(const int* __restrict__ ei) {
    int e = blockIdx.x * blockDim.x + threadIdx.x;
    if (e < N_EDGES) atomicAdd(&g_deg[ei[N_EDGES + e]], 1);   // dst = ei[1]
}

// ---------------- scan pass 1 (+ fused dinv) ---------------------------------
__global__ __launch_bounds__(SCAN_B) void k_scan1() {
    __shared__ int wsum[32];
    int t = threadIdx.x, lane = t & 31, wid = t >> 5;
    int idx = blockIdx.x * SCAN_B + t;
    int v = (idx < N_NODES) ? g_deg[idx] : 0;
    int x = v;
#pragma unroll
    for (int off = 1; off < 32; off <<= 1) {
        int n = __shfl_up_sync(0xffffffffu, x, off);
        if (lane >= off) x += n;
    }
    if (lane == 31) wsum[wid] = x;
    __syncthreads();
    if (wid == 0) {
        int w = wsum[lane];
#pragma unroll
        for (int off = 1; off < 32; off <<= 1) {
            int n = __shfl_up_sync(0xffffffffu, w, off);
            if (lane >= off) w += n;
        }
        wsum[lane] = w;
    }
    __syncthreads();
    int warpoff = (wid > 0) ? wsum[wid - 1] : 0;
    int excl = x - v + warpoff;
    if (idx < N_NODES) {
        g_rowptr[idx] = excl;
        g_dinv[idx]   = rsqrtf((float)(v + 1));   // +1 self loop
    }
    if (t == SCAN_B - 1) g_bsum[blockIdx.x] = warpoff + x;
}

// ---------------- scan pass 2 ------------------------------------------------
__global__ __launch_bounds__(256) void k_scan2() {
    __shared__ int wsum[8];
    int t = threadIdx.x, lane = t & 31, wid = t >> 5;
    int v = (t < SCAN_NB) ? g_bsum[t] : 0;
    int x = v;
#pragma unroll
    for (int off = 1; off < 32; off <<= 1) {
        int n = __shfl_up_sync(0xffffffffu, x, off);
        if (lane >= off) x += n;
    }
    if (lane == 31) wsum[wid] = x;
    __syncthreads();
    if (wid == 0 && lane < 8) {
        int w = wsum[lane];
#pragma unroll
        for (int off = 1; off < 8; off <<= 1) {
            int n = __shfl_up_sync(0xffu, w, off);
            if (lane >= off) w += n;
        }
        wsum[lane] = w;
    }
    __syncthreads();
    int warpoff = (wid > 0) ? wsum[wid - 1] : 0;
    int excl = x - v + warpoff;
    if (t < SCAN_NB) g_bsum[t] = excl;
    if (t == SCAN_NB - 1) g_rowptr[N_NODES] = excl + v;
}

// ---------------- scan pass 3 ------------------------------------------------
__global__ __launch_bounds__(SCAN_B) void k_scan3() {
    int idx = blockIdx.x * SCAN_B + threadIdx.x;
    if (idx < N_NODES) {
        int r = g_rowptr[idx] + g_bsum[blockIdx.x];
        g_rowptr[idx] = r;
        g_cursor[idx] = r;
    }
}

// -------- GEMM1 (tensor core) + fused CSR scatter ----------------------------
// hs1 = (x @ W1) * dinv -> fp16 ; then this block scatters a 4096-edge slice.
#define XS_STRIDE 57    // half2 words per row (56 data + 1 pad, odd stride)
__global__ __launch_bounds__(256) void k_gemm1(const float* __restrict__ x,
                                               const float* __restrict__ W1,
                                               const int* __restrict__ ei) {
    __shared__ __half2 Xs[128 * XS_STRIDE];  // 29.2 KB
    __shared__ __half2 Wsm[56 * 72];         // 16.1 KB  (k-pair, n)
    int t = threadIdx.x;
    int rbase = blockIdx.x * 128;

    // W staging: (kp, n) incremental (256 = 3*72+40)
    {
        int kp = t / 72, n = t - kp * 72;
        for (int idx = t; idx < 56 * 72; idx += 256) {
            int k0 = 2 * kp;
            float lo = (k0 < D_IN && n < D_H1) ? W1[k0 * D_H1 + n] : 0.0f;
            float hi = (k0 + 1 < D_IN && n < D_H1) ? W1[(k0 + 1) * D_H1 + n] : 0.0f;
            Wsm[kp * 72 + n] = __floats2half2_rn(lo, hi);
            kp += 3; n += 40;
            if (n >= 72) { n -= 72; kp += 1; }
        }
    }

    // X staging: (rr, kp) incremental (256 = 4*56+32)
    {
        int rr = t / 56, kp = t - rr * 56;
        for (int idx = t; idx < 128 * 56; idx += 256) {
            int row = rbase + rr;
            __half2 v = __floats2half2_rn(0.0f, 0.0f);
            if (row < N_NODES && kp < 50) {
                float2 f2 = *(const float2*)(x + (size_t)row * D_IN + 2 * kp);
                v = __floats2half2_rn(f2.x, f2.y);
            }
            Xs[rr * XS_STRIDE + kp] = v;
            rr += 4; kp += 32;
            if (kp >= 56) { kp -= 56; rr += 1; }
        }
    }
    __syncthreads();

    int w    = t >> 5;
    int lane = t & 31;
    int g    = lane >> 2;
    int tig  = lane & 3;
    int m0   = w * 16;

    float acc[9][4];
#pragma unroll
    for (int nt = 0; nt < 9; nt++)
#pragma unroll
        for (int j = 0; j < 4; j++) acc[nt][j] = 0.0f;

    const unsigned* XsU = (const unsigned*)Xs;
    const unsigned* WsU = (const unsigned*)Wsm;

#pragma unroll
    for (int ks = 0; ks < 7; ks++) {
        int kb = ks * 8;
        unsigned a0 = XsU[(m0 + g)     * XS_STRIDE + kb + tig];
        unsigned a1 = XsU[(m0 + g + 8) * XS_STRIDE + kb + tig];
        unsigned a2 = XsU[(m0 + g)     * XS_STRIDE + kb + 4 + tig];
        unsigned a3 = XsU[(m0 + g + 8) * XS_STRIDE + kb + 4 + tig];
#pragma unroll
        for (int nt = 0; nt < 9; nt++) {
            unsigned b0 = WsU[(kb + tig)     * 72 + nt * 8 + g];
            unsigned b1 = WsU[(kb + 4 + tig) * 72 + nt * 8 + g];
            asm volatile(
                "mma.sync.aligned.m16n8k16.row.col.f32.f16.f16.f32 "
                "{%0,%1,%2,%3}, {%4,%5,%6,%7}, {%8,%9}, {%0,%1,%2,%3};"
                : "+f"(acc[nt][0]), "+f"(acc[nt][1]),
                  "+f"(acc[nt][2]), "+f"(acc[nt][3])
                : "r"(a0), "r"(a1), "r"(a2), "r"(a3), "r"(b0), "r"(b1));
        }
    }

    __half2* h2out = (__half2*)g_h1h;          // row stride 36 half2
    int row0 = rbase + m0 + g;
    int row1 = row0 + 8;
    float d0 = (row0 < N_NODES) ? g_dinv[row0] : 0.0f;
    float d1 = (row1 < N_NODES) ? g_dinv[row1] : 0.0f;
#pragma unroll
    for (int nt = 0; nt < 9; nt++) {
        int cw = nt * 4 + tig;
        if (row0 < N_NODES)
            h2out[(unsigned)row0 * 36 + cw] =
                __floats2half2_rn(acc[nt][0] * d0, acc[nt][1] * d0);
        if (row1 < N_NODES)
            h2out[(unsigned)row1 * 36 + cw] =
                __floats2half2_rn(acc[nt][2] * d1, acc[nt][3] * d1);
    }

    // -------- fused CSR scatter: this block's 4096-edge slice ---------------
    {
        int base = blockIdx.x * 4096;
        int lim  = base + 4096;
        if (lim > N_EDGES) lim = N_EDGES;
        for (int e = base + t; e < lim; e += 256) {
            int s = __ldg(&ei[e]);
            int d = __ldg(&ei[N_EDGES + e]);
            int pos = atomicAdd(&g_cursor[d], 1);
            g_esrc[pos] = s;
        }
    }
}

// ---------------- fp16 chunk accumulate --------------------------------------
__device__ __forceinline__ void acc_chunk(float* a, uint4 q) {
    const __half2* hp = (const __half2*)&q;
#pragma unroll
    for (int j = 0; j < 4; j++) {
        float2 f = __half22float2(hp[j]);
        a[2 * j]     += f.x;
        a[2 * j + 1] += f.y;
    }
}

// ------ agg1: a1h[i] = fp16( relu( dinv[i]*(hs1[i] + sum hs1[src]) + b1 ) ) --
__global__ __launch_bounds__(288) void k_agg1(const float* __restrict__ b1) {
    int t  = threadIdx.x;
    int ln = t / 9;
    int c  = t - ln * 9;
    int i  = blockIdx.x * 32 + ln;
    if (i >= N_NODES) return;

    const uint4* hs = (const uint4*)g_h1h;      // N x 9 chunks
    int beg = __ldg(&g_rowptr[i]);
    int end = __ldg(&g_rowptr[i + 1]);

    float a[8] = {0, 0, 0, 0, 0, 0, 0, 0};
    acc_chunk(a, __ldg(&hs[(unsigned)i * 9 + c]));      // self loop

    int k = beg;
    for (; k + 3 < end; k += 4) {
        int s0 = __ldg(&g_esrc[k]);
        int s1 = __ldg(&g_esrc[k + 1]);
        int s2 = __ldg(&g_esrc[k + 2]);
        int s3 = __ldg(&g_esrc[k + 3]);
        uint4 q0 = __ldg(&hs[(unsigned)s0 * 9 + c]);
        uint4 q1 = __ldg(&hs[(unsigned)s1 * 9 + c]);
        uint4 q2 = __ldg(&hs[(unsigned)s2 * 9 + c]);
        uint4 q3 = __ldg(&hs[(unsigned)s3 * 9 + c]);
        acc_chunk(a, q0); acc_chunk(a, q1); acc_chunk(a, q2); acc_chunk(a, q3);
    }
    for (; k < end; k++) {
        int s = __ldg(&g_esrc[k]);
        acc_chunk(a, __ldg(&hs[(unsigned)s * 9 + c]));
    }

    float d = __ldg(&g_dinv[i]);
    uint4 u;
    __half2* hp = (__half2*)&u;
#pragma unroll
    for (int j = 0; j < 4; j++) {
        int col = 8 * c + 2 * j;
        float bv0 = (col     < D_H1) ? __ldg(b1 + col)     : 0.0f;
        float bv1 = (col + 1 < D_H1) ? __ldg(b1 + col + 1) : 0.0f;
        float v0 = fmaxf(d * a[2 * j]     + bv0, 0.0f);
        float v1 = fmaxf(d * a[2 * j + 1] + bv1, 0.0f);
        hp[j] = __floats2half2_rn(v0, v1);
    }
    g_a1h[(unsigned)i * 9 + c] = u;
}

// ---------------- GEMM2 (tensor core): hs2 = (a1h @ W2) * dinv -> fp16 ------
#define XS2_STRIDE 41   // half2 words per row (40 data + 1 pad, odd stride)
__global__ __launch_bounds__(256) void k_gemm2(const float* __restrict__ W2) {
    __shared__ __half2 Xs[128 * XS2_STRIDE]; // 21.0 KB
    __shared__ __half2 Wsm[40 * 72];         // 11.5 KB
    int t = threadIdx.x;
    int rbase = blockIdx.x * 128;

    // W staging incremental (256 = 3*72+40)
    {
        int kp = t / 72, n = t - kp * 72;
        for (int idx = t; idx < 40 * 72; idx += 256) {
            int k0 = 2 * kp;
            float lo = (k0 < D_H1 && n < D_H2) ? W2[k0 * D_H2 + n] : 0.0f;
            float hi = (k0 + 1 < D_H1 && n < D_H2) ? W2[(k0 + 1) * D_H2 + n] : 0.0f;
            Wsm[kp * 72 + n] = __floats2half2_rn(lo, hi);
            kp += 3; n += 40;
            if (n >= 72) { n -= 72; kp += 1; }
        }
    }

    // X staging incremental (256 = 6*40+16)
    {
        const __half2* a1 = (const __half2*)g_a1h;   // row stride 36 half2
        int rr = t / 40, kp = t - rr * 40;
        for (int idx = t; idx < 128 * 40; idx += 256) {
            int row = rbase + rr;
            __half2 v = __floats2half2_rn(0.0f, 0.0f);
            if (row < N_NODES && kp < 36) v = a1[(unsigned)row * 36 + kp];
            Xs[rr * XS2_STRIDE + kp] = v;
            rr += 6; kp += 16;
            if (kp >= 40) { kp -= 40; rr += 1; }
        }
    }
    __syncthreads();

    int w    = t >> 5;
    int lane = t & 31;
    int g    = lane >> 2;
    int tig  = lane & 3;
    int m0   = w * 16;

    float acc[8][4];
#pragma unroll
    for (int nt = 0; nt < 8; nt++)
#pragma unroll
        for (int j = 0; j < 4; j++) acc[nt][j] = 0.0f;

    const unsigned* XsU = (const unsigned*)Xs;
    const unsigned* WsU = (const unsigned*)Wsm;

#pragma unroll
    for (int ks = 0; ks < 5; ks++) {
        int kb = ks * 8;
        unsigned a0 = XsU[(m0 + g)     * XS2_STRIDE + kb + tig];
        unsigned a1r= XsU[(m0 + g + 8) * XS2_STRIDE + kb + tig];
        unsigned a2 = XsU[(m0 + g)     * XS2_STRIDE + kb + 4 + tig];
        unsigned a3 = XsU[(m0 + g + 8) * XS2_STRIDE + kb + 4 + tig];
#pragma unroll
        for (int nt = 0; nt < 8; nt++) {
            unsigned b0 = WsU[(kb + tig)     * 72 + nt * 8 + g];
            unsigned b1 = WsU[(kb + 4 + tig) * 72 + nt * 8 + g];
            asm volatile(
                "mma.sync.aligned.m16n8k16.row.col.f32.f16.f16.f32 "
                "{%0,%1,%2,%3}, {%4,%5,%6,%7}, {%8,%9}, {%0,%1,%2,%3};"
                : "+f"(acc[nt][0]), "+f"(acc[nt][1]),
                  "+f"(acc[nt][2]), "+f"(acc[nt][3])
                : "r"(a0), "r"(a1r), "r"(a2), "r"(a3), "r"(b0), "r"(b1));
        }
    }

    __half2* h2out = (__half2*)g_h2h;          // row stride 32 half2
    int row0 = rbase + m0 + g;
    int row1 = row0 + 8;
    float d0 = (row0 < N_NODES) ? g_dinv[row0] : 0.0f;
    float d1 = (row1 < N_NODES) ? g_dinv[row1] : 0.0f;
#pragma unroll
    for (int nt = 0; nt < 8; nt++) {
        int cw = nt * 4 + tig;
        if (row0 < N_NODES)
            h2out[(unsigned)row0 * 32 + cw] =
                __floats2half2_rn(acc[nt][0] * d0, acc[nt][1] * d0);
        if (row1 < N_NODES)
            h2out[(unsigned)row1 * 32 + cw] =
                __floats2half2_rn(acc[nt][2] * d1, acc[nt][3] * d1);
    }
}

// ------- agg2 + output fused: out[i]=relu(sum_c relu(agg2_c+b2)*Wout + bout) -
__global__ __launch_bounds__(256) void k_agg2out(const float* __restrict__ b2,
                                                 const float* __restrict__ Wout,
                                                 const float* __restrict__ bout,
                                                 float* __restrict__ out) {
    int t  = threadIdx.x;
    int ln = t >> 3;
    int c  = t & 7;
    int i  = blockIdx.x * 32 + ln;
    if (i >= N_NODES) return;

    const uint4* hs = (const uint4*)g_h2h;      // N x 8 chunks
    int beg = __ldg(&g_rowptr[i]);
    int end = __ldg(&g_rowptr[i + 1]);

    float a[8] = {0, 0, 0, 0, 0, 0, 0, 0};
    acc_chunk(a, __ldg(&hs[(unsigned)i * 8 + c]));      // self loop

    int k = beg;
    for (; k + 3 < end; k += 4) {
        int s0 = __ldg(&g_esrc[k]);
        int s1 = __ldg(&g_esrc[k + 1]);
        int s2 = __ldg(&g_esrc[k + 2]);
        int s3 = __ldg(&g_esrc[k + 3]);
        uint4 q0 = __ldg(&hs[(unsigned)s0 * 8 + c]);
        uint4 q1 = __ldg(&hs[(unsigned)s1 * 8 + c]);
        uint4 q2 = __ldg(&hs[(unsigned)s2 * 8 + c]);
        uint4 q3 = __ldg(&hs[(unsigned)s3 * 8 + c]);
        acc_chunk(a, q0); acc_chunk(a, q1); acc_chunk(a, q2); acc_chunk(a, q3);
    }
    for (; k < end; k++) {
        int s = __ldg(&g_esrc[k]);
        acc_chunk(a, __ldg(&hs[(unsigned)s * 8 + c]));
    }

    float d = __ldg(&g_dinv[i]);
    float4 b2a = __ldg((const float4*)b2 + c * 2);
    float4 b2b = __ldg((const float4*)b2 + c * 2 + 1);
    float4 woa = __ldg((const float4*)Wout + c * 2);
    float4 wob = __ldg((const float4*)Wout + c * 2 + 1);

    float s = fmaxf(d * a[0] + b2a.x, 0.0f) * woa.x
            + fmaxf(d * a[1] + b2a.y, 0.0f) * woa.y
            + fmaxf(d * a[2] + b2a.z, 0.0f) * woa.z
            + fmaxf(d * a[3] + b2a.w, 0.0f) * woa.w
            + fmaxf(d * a[4] + b2b.x, 0.0f) * wob.x
            + fmaxf(d * a[5] + b2b.y, 0.0f) * wob.y
            + fmaxf(d * a[6] + b2b.z, 0.0f) * wob.z
            + fmaxf(d * a[7] + b2b.w, 0.0f) * wob.w;

    s += __shfl_xor_sync(0xffffffffu, s, 1);
    s += __shfl_xor_sync(0xffffffffu, s, 2);
    s += __shfl_xor_sync(0xffffffffu, s, 4);
    if (c == 0) out[i] = fmaxf(s + __ldg(bout), 0.0f);
}

// ---------------- launch ----------------------------------------------------
extern "C" void kernel_launch(void* const* d_in, const int* in_sizes, int n_in,
                              void* d_out, int out_size) {
    const float* x    = (const float*)d_in[0];
    const int*   ei   = (const int*)  d_in[1];
    const float* W1   = (const float*)d_in[2];
    const float* b1   = (const float*)d_in[3];
    const float* W2   = (const float*)d_in[4];
    const float* b2   = (const float*)d_in[5];
    const float* Wout = (const float*)d_in[6];
    const float* bout = (const float*)d_in[7];
    float* out = (float*)d_out;

    const int NB_N = (N_NODES + 255) / 256;
    const int NB_E = (N_EDGES + 255) / 256;
    const int NB_G = (N_NODES + 127) / 128;   // 1563 blocks, 128 rows each
    const int NB_A = (N_NODES + 31) / 32;     // 6250

    k_deg_zero <<<NB_N, 256>>>();
    k_deg_count<<<NB_E, 256>>>(ei);
    k_scan1    <<<SCAN_NB, SCAN_B>>>();       // also computes dinv
    k_scan2    <<<1, 256>>>();
    k_scan3    <<<SCAN_NB, SCAN_B>>>();
    k_gemm1    <<<NB_G, 256>>>(x, W1, ei);    // MMA + fused CSR scatter
    k_agg1     <<<NB_A, 288>>>(b1);
    k_gemm2    <<<NB_G, 256>>>(W2);
    k_agg2out  <<<NB_A, 256>>>(b2, Wout, bout, out);
}